// round 6
// baseline (speedup 1.0000x reference)
#include <cuda_runtime.h>
#include <cuda_fp16.h>
#include <math.h>

#define HIDDEN 1152
#define HEADS  16
#define HD     72
#define BATCH  16
#define SEQ    1024
#define M_TOT  (BATCH*SEQ)
#define N_QKV  (3*HIDDEN)
#define QSCALE 0.11785113f
#define RMS_EPS 1.1920928955078125e-07f

// ---------------- scratch ----------------
__device__ __align__(256) __half g_qh[(size_t)BATCH*HEADS*SEQ*HD];
__device__ __align__(256) __half g_kh[(size_t)BATCH*HEADS*SEQ*HD];
__device__ __align__(256) __half g_vh[(size_t)BATCH*HEADS*SEQ*HD];
__device__ __align__(256) __half g_ah[(size_t)M_TOT*HIDDEN];
__device__ __align__(256) __half g_xh[(size_t)M_TOT*HIDDEN];
__device__ __align__(256) __half g_wqh[(size_t)N_QKV*HIDDEN];
__device__ __align__(256) __half g_wph[(size_t)HIDDEN*HIDDEN];

// ---------------- helpers ----------------
__device__ __forceinline__ unsigned h2u(__half2 h) {
    unsigned u;
    asm("mov.b32 %0, %1;" : "=r"(u) : "r"(*(unsigned*)&h));
    return u;
}
__device__ __forceinline__ unsigned sptr(const void* p) {
    return (unsigned)__cvta_generic_to_shared(p);
}
__device__ __forceinline__ void ldsm4(unsigned r[4], const void* p) {
    asm volatile("ldmatrix.sync.aligned.m8n8.x4.shared.b16 {%0,%1,%2,%3},[%4];"
                 : "=r"(r[0]), "=r"(r[1]), "=r"(r[2]), "=r"(r[3]) : "r"(sptr(p)));
}
__device__ __forceinline__ void ldsm4t(unsigned r[4], const void* p) {
    asm volatile("ldmatrix.sync.aligned.m8n8.x4.trans.shared.b16 {%0,%1,%2,%3},[%4];"
                 : "=r"(r[0]), "=r"(r[1]), "=r"(r[2]), "=r"(r[3]) : "r"(sptr(p)));
}
__device__ __forceinline__ void ldsm2t(unsigned r[2], const void* p) {
    asm volatile("ldmatrix.sync.aligned.m8n8.x2.trans.shared.b16 {%0,%1},[%2];"
                 : "=r"(r[0]), "=r"(r[1]) : "r"(sptr(p)));
}
__device__ __forceinline__ void mma16816(float c[4], const unsigned a[4],
                                         unsigned b0, unsigned b1) {
    asm volatile(
        "mma.sync.aligned.m16n8k16.row.col.f32.f16.f16.f32 "
        "{%0,%1,%2,%3},{%4,%5,%6,%7},{%8,%9},{%0,%1,%2,%3};"
        : "+f"(c[0]), "+f"(c[1]), "+f"(c[2]), "+f"(c[3])
        : "r"(a[0]), "r"(a[1]), "r"(a[2]), "r"(a[3]), "r"(b0), "r"(b1));
}
__device__ __forceinline__ void cp16(void* smem, const void* g) {
    asm volatile("cp.async.ca.shared.global [%0], [%1], 16;" :: "r"(sptr(smem)), "l"(g));
}
__device__ __forceinline__ void cp_commit() { asm volatile("cp.async.commit_group;"); }
__device__ __forceinline__ void cp_wait1()  { asm volatile("cp.async.wait_group 1;"); }
__device__ __forceinline__ void cp_wait2()  { asm volatile("cp.async.wait_group 2;"); }

// ---------------- fp32 -> fp16 conversion ----------------
__global__ __launch_bounds__(256) void conv_h_kernel(const float4* __restrict__ src,
                                                     uint4* __restrict__ dst, int n8) {
    int i = blockIdx.x * 256 + threadIdx.x;
    if (i < n8) {
        float4 f0 = src[2*i], f1 = src[2*i+1];
        uint4 o;
        o.x = h2u(__floats2half2_rn(f0.x, f0.y));
        o.y = h2u(__floats2half2_rn(f0.z, f0.w));
        o.z = h2u(__floats2half2_rn(f1.x, f1.y));
        o.w = h2u(__floats2half2_rn(f1.z, f1.w));
        dst[i] = o;
    }
}

// =======================================================================
// fp16 GEMM: BM=256 BN=128 BK=64, 512 threads = 16 warps (4x4),
// warp tile 64x32, 3-stage cp.async, XOR-swizzled smem.
// =======================================================================
#define GA_ST 16384   // halves per A stage
#define GB_ST 8192    // halves per B stage
#define GEMM_SMEM (3*(GA_ST+GB_ST)*2)   // 147456 bytes

__global__ __launch_bounds__(512) void gemm_f16_kernel(const __half* __restrict__ A,
                                                       const __half* __restrict__ W,
                                                       const float* __restrict__ bias,
                                                       float* __restrict__ out,
                                                       int mode) {
    extern __shared__ __half hsm[];
    __half* As = hsm;
    __half* Bs = hsm + 3*GA_ST;

    const int tid  = threadIdx.x;
    const int warp = tid >> 5;
    const int wr   = warp >> 2;     // 0..3
    const int wc   = warp & 3;      // 0..3
    const int lane = tid & 31;
    const int g    = lane >> 2;
    const int t    = lane & 3;

    const int m0 = blockIdx.y * 256;
    const int n0 = blockIdx.x * 128;

    float acc[4][4][4];
#pragma unroll
    for (int mi = 0; mi < 4; ++mi)
#pragma unroll
        for (int ni = 0; ni < 4; ++ni)
#pragma unroll
            for (int r = 0; r < 4; ++r) acc[mi][ni][r] = 0.f;

    const int NS = HIDDEN / 64;   // 18

    auto load_stage = [&](int s) {
        __half* dA = As + (s % 3) * GA_ST;
        __half* dB = Bs + (s % 3) * GB_ST;
        const int kt = s * 64;
#pragma unroll
        for (int p = 0; p < 4; ++p) {
            const int idx = tid + p * 512;
            const int row = idx >> 3, c = idx & 7, pc = c ^ (row & 7);
            cp16(dA + (row*8 + pc)*8, A + (size_t)(m0 + row) * HIDDEN + kt + c*8);
        }
#pragma unroll
        for (int p = 0; p < 2; ++p) {
            const int idx = tid + p * 512;
            const int row = idx >> 3, c = idx & 7, pc = c ^ (row & 7);
            cp16(dB + (row*8 + pc)*8, W + (size_t)(n0 + row) * HIDDEN + kt + c*8);
        }
    };

    load_stage(0); cp_commit();
    load_stage(1); cp_commit();

    const int a_rin  = lane & 15;
    const int a_koff = lane >> 4;
    const int b_nin  = (lane & 7) + ((lane >> 4) << 3);
    const int b_koff = (lane >> 3) & 1;

    for (int s = 0; s < NS; ++s) {
        if (s + 2 < NS) load_stage(s + 2);
        cp_commit();
        cp_wait2();
        __syncthreads();
        const __half* cA = As + (s % 3) * GA_ST;
        const __half* cB = Bs + (s % 3) * GB_ST;
#pragma unroll
        for (int ks = 0; ks < 4; ++ks) {
            unsigned a[4][4];
#pragma unroll
            for (int mi = 0; mi < 4; ++mi) {
                const int row = wr*64 + mi*16 + a_rin;
                const int pc  = (ks*2 + a_koff) ^ (row & 7);
                ldsm4(a[mi], cA + (row*8 + pc)*8);
            }
            unsigned bf[4][2];
#pragma unroll
            for (int p = 0; p < 2; ++p) {
                const int row = wc*32 + p*16 + b_nin;
                const int pc  = (ks*2 + b_koff) ^ (row & 7);
                unsigned q[4];
                ldsm4(q, cB + (row*8 + pc)*8);
                bf[2*p][0] = q[0]; bf[2*p][1] = q[1];
                bf[2*p+1][0] = q[2]; bf[2*p+1][1] = q[3];
            }
#pragma unroll
            for (int mi = 0; mi < 4; ++mi)
#pragma unroll
                for (int ni = 0; ni < 4; ++ni)
                    mma16816(acc[mi][ni], a[mi], bf[ni][0], bf[ni][1]);
        }
        __syncthreads();
    }

    // ---------------- epilogue ----------------
    if (mode == 0) {
        const int which = n0 / HIDDEN;
        __half* dst = (which == 0) ? g_qh : (which == 1) ? g_kh : g_vh;
#pragma unroll
        for (int mi = 0; mi < 4; ++mi)
#pragma unroll
            for (int ni = 0; ni < 4; ++ni) {
                const int col = n0 + wc*32 + ni*8 + 2*t;
                const int rem = col - which * HIDDEN;
                const int h   = rem / HD;
                const int d   = rem - h * HD;
                const float b0 = bias[col], b1 = bias[col + 1];
#pragma unroll
                for (int half_ = 0; half_ < 2; ++half_) {
                    const int row = m0 + wr*64 + mi*16 + g + half_*8;
                    const int bi  = row >> 10, si = row & (SEQ - 1);
                    __half2 v = __floats2half2_rn(acc[mi][ni][2*half_] + b0,
                                                  acc[mi][ni][2*half_+1] + b1);
                    *(__half2*)&dst[(((size_t)(bi*HEADS + h))*SEQ + si)*HD + d] = v;
                }
            }
    } else {
#pragma unroll
        for (int mi = 0; mi < 4; ++mi)
#pragma unroll
            for (int ni = 0; ni < 4; ++ni) {
                const int col = n0 + wc*32 + ni*8 + 2*t;
                const float b0 = bias[col], b1 = bias[col + 1];
#pragma unroll
                for (int half_ = 0; half_ < 2; ++half_) {
                    const int row = m0 + wr*64 + mi*16 + g + half_*8;
                    float2 v = make_float2(acc[mi][ni][2*half_] + b0,
                                           acc[mi][ni][2*half_+1] + b1);
                    *(float2*)&out[(size_t)row * HIDDEN + col] = v;
                }
            }
    }
}

// ---------------- RMSNorm (half in/out), scale folded ----------------
__global__ __launch_bounds__(256) void rmsnorm_h_kernel(__half* __restrict__ tp,
                                                        const float* __restrict__ gamma,
                                                        float scale) {
    const int row  = blockIdx.x * 8 + (threadIdx.x >> 5);
    const int lane = threadIdx.x & 31;
    __half* p = tp + (size_t)row * HD;
    float v0 = __half2float(p[lane]);
    float v1 = __half2float(p[32 + lane]);
    float v2 = (lane < 8) ? __half2float(p[64 + lane]) : 0.f;
    float ss = v0*v0 + v1*v1 + v2*v2;
#pragma unroll
    for (int o = 16; o; o >>= 1) ss += __shfl_xor_sync(0xffffffffu, ss, o);
    const float rs = rsqrtf(ss * (1.0f/72.0f) + RMS_EPS) * scale;
    p[lane]      = __float2half(v0 * rs * gamma[lane]);
    p[32 + lane] = __float2half(v1 * rs * gamma[32 + lane]);
    if (lane < 8) p[64 + lane] = __float2half(v2 * rs * gamma[64 + lane]);
}

// =======================================================================
// fp16 flash attention, NO online max: after RMSNorm (gamma=1),
// |score| <= sqrt(72) by Cauchy-Schwarz, so raw exp is fp32/fp16-safe.
// CTA = (b,h,128 q rows), 8 warps x 16 rows, K/V double-buffered.
// =======================================================================
#define AQ_H (128*80)
#define AK_H (2*64*80)
#define ATTN_SMEM ((AQ_H + 2*AK_H)*2)    // 61440 bytes

__global__ __launch_bounds__(256, 2) void attn_f16_kernel() {
    extern __shared__ __half asm_[];
    __half* Qs = asm_;
    __half* Ks = Qs + AQ_H;
    __half* Vs = Ks + AK_H;

    const int qt = blockIdx.x;
    const int h  = blockIdx.y;
    const int b  = blockIdx.z;
    const int tid  = threadIdx.x;
    const int warp = tid >> 5;
    const int lane = tid & 31;
    const int g    = lane >> 2;
    const int t    = lane & 3;

    const size_t head_base = ((size_t)(b*HEADS + h)) * SEQ * HD;
    const __half* gQ = g_qh + head_base + (size_t)qt * 128 * HD;
    const __half* gK = g_kh + head_base;
    const __half* gV = g_vh + head_base;

    for (int r = tid; r < 384; r += 256) {
        __half* base = (r < 128) ? Qs : (r < 256) ? Ks : Vs;
        const int rr = r & 127;
        *(uint4*)&base[(rr*10 + 9)*8] = make_uint4(0,0,0,0);
    }
    for (int idx = tid; idx < 1152; idx += 256) {
        const int row = idx / 9, c = idx - row*9;
        const int pc = (c < 8) ? (c ^ (row & 7)) : 8;
        cp16(Qs + (row*10 + pc)*8, gQ + row*HD + c*8);
    }
    auto load_kv = [&](int kt) {
        __half* Kb = Ks + (kt & 1) * 64*80;
        __half* Vb = Vs + (kt & 1) * 64*80;
        const size_t base = (size_t)kt * 64 * HD;
        for (int idx = tid; idx < 1152; idx += 256) {
            const int arr = idx >= 576;
            const int rem = idx - 576*arr;
            const int row = rem / 9, c = rem - row*9;
            const int pc = (c < 8) ? (c ^ (row & 7)) : 8;
            if (arr) cp16(Vb + (row*10 + pc)*8, gV + base + row*HD + c*8);
            else     cp16(Kb + (row*10 + pc)*8, gK + base + row*HD + c*8);
        }
    };
    load_kv(0);
    cp_commit();

    float o[9][4];
#pragma unroll
    for (int n = 0; n < 9; ++n)
#pragma unroll
        for (int r = 0; r < 4; ++r) o[n][r] = 0.f;
    float l0 = 0.f, l1 = 0.f;

    const int a_rin  = lane & 15;
    const int a_koff = lane >> 4;
    const int b_nin  = (lane & 7) + ((lane >> 4) << 3);
    const int b_koff = (lane >> 3) & 1;
    const int v_sin  = (lane & 7) + ((lane >> 3) & 1) * 8;
    const int v_doff = lane >> 4;

    for (int kt = 0; kt < SEQ/64; ++kt) {
        if (kt + 1 < SEQ/64) load_kv(kt + 1);
        cp_commit();
        cp_wait1();
        __syncthreads();
        const __half* Kb = Ks + (kt & 1) * 64*80;
        const __half* Vb = Vs + (kt & 1) * 64*80;

        // ---- S = Q @ K^T ----
        float c[8][4];
#pragma unroll
        for (int n = 0; n < 8; ++n)
#pragma unroll
            for (int r = 0; r < 4; ++r) c[n][r] = 0.f;
#pragma unroll
        for (int ks = 0; ks < 5; ++ks) {
            unsigned aq[4];
            {
                const int row = warp*16 + a_rin;
                const int ch  = 2*ks + a_koff;
                const int pc  = (ch < 8) ? (ch ^ (row & 7)) : ch;
                ldsm4(aq, Qs + (row*10 + pc)*8);
            }
#pragma unroll
            for (int p = 0; p < 4; ++p) {
                const int row = p*16 + b_nin;
                const int ch  = 2*ks + b_koff;
                const int pc  = (ch < 8) ? (ch ^ (row & 7)) : ch;
                unsigned q[4];
                ldsm4(q, Kb + (row*10 + pc)*8);
                mma16816(c[2*p],   aq, q[0], q[1]);
                mma16816(c[2*p+1], aq, q[2], q[3]);
            }
        }

        // ---- softmax, no max subtraction (scores bounded by sqrt(72)) ----
        float sum0 = 0.f, sum1 = 0.f;
#pragma unroll
        for (int n = 0; n < 8; ++n) {
            c[n][0] = __expf(c[n][0]);
            c[n][1] = __expf(c[n][1]);
            c[n][2] = __expf(c[n][2]);
            c[n][3] = __expf(c[n][3]);
            sum0 += c[n][0] + c[n][1];
            sum1 += c[n][2] + c[n][3];
        }
        sum0 += __shfl_xor_sync(0xffffffffu, sum0, 1);
        sum0 += __shfl_xor_sync(0xffffffffu, sum0, 2);
        sum1 += __shfl_xor_sync(0xffffffffu, sum1, 1);
        sum1 += __shfl_xor_sync(0xffffffffu, sum1, 2);
        l0 += sum0;
        l1 += sum1;

        // repack P -> A-frags (fp16; max ~4.9e3 << 65504)
        unsigned pa[4][4];
#pragma unroll
        for (int k2 = 0; k2 < 4; ++k2) {
            pa[k2][0] = h2u(__floats2half2_rn(c[2*k2][0],   c[2*k2][1]));
            pa[k2][1] = h2u(__floats2half2_rn(c[2*k2][2],   c[2*k2][3]));
            pa[k2][2] = h2u(__floats2half2_rn(c[2*k2+1][0], c[2*k2+1][1]));
            pa[k2][3] = h2u(__floats2half2_rn(c[2*k2+1][2], c[2*k2+1][3]));
        }

        // ---- O += P @ V ----
#pragma unroll
        for (int k2 = 0; k2 < 4; ++k2) {
#pragma unroll
            for (int p2 = 0; p2 < 4; ++p2) {
                const int srow = k2*16 + v_sin;
                const int ch   = 2*p2 + v_doff;
                const int pc   = ch ^ (srow & 7);
                unsigned q[4];
                ldsm4t(q, Vb + (srow*10 + pc)*8);
                mma16816(o[2*p2],   pa[k2], q[0], q[1]);
                mma16816(o[2*p2+1], pa[k2], q[2], q[3]);
            }
            {
                const int srow = k2*16 + v_sin;
                unsigned q2[2];
                ldsm2t(q2, Vb + (srow*10 + 8)*8);
                mma16816(o[8], pa[k2], q2[0], q2[1]);
            }
        }
        __syncthreads();
    }

    // ---- epilogue ----
    const float inv0 = 1.0f / l0, inv1 = 1.0f / l1;
    const int q0 = qt*128 + warp*16 + g;
    __half* base0 = g_ah + ((size_t)(b*SEQ + q0)     * HIDDEN) + h*HD;
    __half* base1 = g_ah + ((size_t)(b*SEQ + q0 + 8) * HIDDEN) + h*HD;
#pragma unroll
    for (int n = 0; n < 9; ++n) {
        const int d = n*8 + 2*t;
        *(__half2*)&base0[d] = __floats2half2_rn(o[n][0]*inv0, o[n][1]*inv0);
        *(__half2*)&base1[d] = __floats2half2_rn(o[n][2]*inv1, o[n][3]*inv1);
    }
}

// ---------------- launch ----------------
extern "C" void kernel_launch(void* const* d_in, const int* in_sizes, int n_in,
                              void* d_out, int out_size) {
    const float* x      = (const float*)d_in[0];
    const float* w_qkv  = (const float*)d_in[1];
    const float* b_qkv  = (const float*)d_in[2];
    const float* q_gamma= (const float*)d_in[3];
    const float* k_gamma= (const float*)d_in[4];
    const float* w_proj = (const float*)d_in[5];
    const float* b_proj = (const float*)d_in[6];
    float* out = (float*)d_out;

    cudaFuncSetAttribute(gemm_f16_kernel, cudaFuncAttributeMaxDynamicSharedMemorySize, GEMM_SMEM);
    cudaFuncSetAttribute(attn_f16_kernel, cudaFuncAttributeMaxDynamicSharedMemorySize, ATTN_SMEM);

    __half *xh, *wqh, *wph, *ah, *qh, *kh;
    cudaGetSymbolAddress((void**)&xh,  g_xh);
    cudaGetSymbolAddress((void**)&wqh, g_wqh);
    cudaGetSymbolAddress((void**)&wph, g_wph);
    cudaGetSymbolAddress((void**)&ah,  g_ah);
    cudaGetSymbolAddress((void**)&qh,  g_qh);
    cudaGetSymbolAddress((void**)&kh,  g_kh);

    {   // fp32 -> fp16 conversions
        int n8x = M_TOT*HIDDEN/8, n8q = N_QKV*HIDDEN/8, n8p = HIDDEN*HIDDEN/8;
        conv_h_kernel<<<(n8x+255)/256, 256>>>((const float4*)x, (uint4*)xh, n8x);
        conv_h_kernel<<<(n8q+255)/256, 256>>>((const float4*)w_qkv, (uint4*)wqh, n8q);
        conv_h_kernel<<<(n8p+255)/256, 256>>>((const float4*)w_proj, (uint4*)wph, n8p);
    }
    {   // QKV projection
        dim3 grid(N_QKV/128, M_TOT/256);   // (27, 64)
        gemm_f16_kernel<<<grid, 512, GEMM_SMEM>>>(xh, wqh, b_qkv, nullptr, 0);
    }
    {   // RMSNorm (q gets 1/sqrt(hd) folded in)
        const int rows = BATCH*HEADS*SEQ;
        rmsnorm_h_kernel<<<rows/8, 256>>>(qh, q_gamma, QSCALE);
        rmsnorm_h_kernel<<<rows/8, 256>>>(kh, k_gamma, 1.0f);
    }
    {   // attention
        dim3 grid(SEQ/128, HEADS, BATCH);  // (8,16,16)
        attn_f16_kernel<<<grid, 256, ATTN_SMEM>>>();
    }
    {   // output projection
        dim3 grid(HIDDEN/128, M_TOT/256);  // (9, 64)
        gemm_f16_kernel<<<grid, 512, GEMM_SMEM>>>(ah, wph, b_proj, out, 1);
    }
}

// round 7
// speedup vs baseline: 1.5491x; 1.5491x over previous
#include <cuda_runtime.h>
#include <cuda_fp16.h>
#include <math.h>

#define HIDDEN 1152
#define HEADS  16
#define HD     72
#define BATCH  16
#define SEQ    1024
#define M_TOT  (BATCH*SEQ)
#define N_QKV  (3*HIDDEN)
#define QSCALE 0.11785113f
#define RMS_EPS 1.1920928955078125e-07f

// ---------------- scratch ----------------
__device__ __align__(256) __half g_qh[(size_t)BATCH*HEADS*SEQ*HD];
__device__ __align__(256) __half g_kh[(size_t)BATCH*HEADS*SEQ*HD];
__device__ __align__(256) __half g_vh[(size_t)BATCH*HEADS*SEQ*HD];
__device__ __align__(256) __half g_ah[(size_t)M_TOT*HIDDEN];
__device__ __align__(256) __half g_xh[(size_t)M_TOT*HIDDEN];
__device__ __align__(256) __half g_wqh[(size_t)N_QKV*HIDDEN];
__device__ __align__(256) __half g_wph[(size_t)HIDDEN*HIDDEN];

// ---------------- helpers ----------------
__device__ __forceinline__ unsigned h2u(__half2 h) {
    unsigned u;
    asm("mov.b32 %0, %1;" : "=r"(u) : "r"(*(unsigned*)&h));
    return u;
}
__device__ __forceinline__ unsigned sptr(const void* p) {
    return (unsigned)__cvta_generic_to_shared(p);
}
__device__ __forceinline__ void ldsm4(unsigned r[4], const void* p) {
    asm volatile("ldmatrix.sync.aligned.m8n8.x4.shared.b16 {%0,%1,%2,%3},[%4];"
                 : "=r"(r[0]), "=r"(r[1]), "=r"(r[2]), "=r"(r[3]) : "r"(sptr(p)));
}
__device__ __forceinline__ void ldsm4t(unsigned r[4], const void* p) {
    asm volatile("ldmatrix.sync.aligned.m8n8.x4.trans.shared.b16 {%0,%1,%2,%3},[%4];"
                 : "=r"(r[0]), "=r"(r[1]), "=r"(r[2]), "=r"(r[3]) : "r"(sptr(p)));
}
__device__ __forceinline__ void ldsm2t(unsigned r[2], const void* p) {
    asm volatile("ldmatrix.sync.aligned.m8n8.x2.trans.shared.b16 {%0,%1},[%2];"
                 : "=r"(r[0]), "=r"(r[1]) : "r"(sptr(p)));
}
__device__ __forceinline__ void mma16816(float c[4], const unsigned a[4],
                                         unsigned b0, unsigned b1) {
    asm volatile(
        "mma.sync.aligned.m16n8k16.row.col.f32.f16.f16.f32 "
        "{%0,%1,%2,%3},{%4,%5,%6,%7},{%8,%9},{%0,%1,%2,%3};"
        : "+f"(c[0]), "+f"(c[1]), "+f"(c[2]), "+f"(c[3])
        : "r"(a[0]), "r"(a[1]), "r"(a[2]), "r"(a[3]), "r"(b0), "r"(b1));
}
__device__ __forceinline__ void cp16(void* smem, const void* g) {
    asm volatile("cp.async.ca.shared.global [%0], [%1], 16;" :: "r"(sptr(smem)), "l"(g));
}
__device__ __forceinline__ void cp_commit() { asm volatile("cp.async.commit_group;"); }
__device__ __forceinline__ void cp_wait0()  { asm volatile("cp.async.wait_group 0;"); }
__device__ __forceinline__ void cp_wait1()  { asm volatile("cp.async.wait_group 1;"); }

// ---------------- fp32 -> fp16 conversion ----------------
__global__ __launch_bounds__(256) void conv_h_kernel(const float4* __restrict__ src,
                                                     uint4* __restrict__ dst, int n8) {
    int i = blockIdx.x * 256 + threadIdx.x;
    if (i < n8) {
        float4 f0 = src[2*i], f1 = src[2*i+1];
        uint4 o;
        o.x = h2u(__floats2half2_rn(f0.x, f0.y));
        o.y = h2u(__floats2half2_rn(f0.z, f0.w));
        o.z = h2u(__floats2half2_rn(f1.x, f1.y));
        o.w = h2u(__floats2half2_rn(f1.z, f1.w));
        dst[i] = o;
    }
}

// =======================================================================
// fp16 GEMM: BM=256 BN=128 BK=128, 256 threads = 8 warps (4x2),
// warp tile 64x64, 2-stage cp.async, XOR-swizzled smem (16B chunks,
// 256B rows = two 128B swizzle sub-blocks).
// =======================================================================
#define GA_ST 32768   // halves per A stage (256*128)
#define GB_ST 16384   // halves per B stage (128*128)
#define GEMM_SMEM (2*(GA_ST+GB_ST)*2)   // 196608 bytes

__global__ __launch_bounds__(256) void gemm_f16_kernel(const __half* __restrict__ A,
                                                       const __half* __restrict__ W,
                                                       const float* __restrict__ bias,
                                                       float* __restrict__ out,
                                                       int mode) {
    extern __shared__ __half hsm[];
    __half* As = hsm;
    __half* Bs = hsm + 2*GA_ST;

    const int tid  = threadIdx.x;
    const int warp = tid >> 5;
    const int wr   = warp >> 1;     // 0..3
    const int wc   = warp & 1;      // 0..1
    const int lane = tid & 31;
    const int g    = lane >> 2;
    const int t    = lane & 3;

    const int m0 = blockIdx.y * 256;
    const int n0 = blockIdx.x * 128;

    float acc[4][8][4];
#pragma unroll
    for (int mi = 0; mi < 4; ++mi)
#pragma unroll
        for (int ni = 0; ni < 8; ++ni)
#pragma unroll
            for (int r = 0; r < 4; ++r) acc[mi][ni][r] = 0.f;

    const int NS = HIDDEN / 128;   // 9

    // rows are 128 halves = 256B = 16 chunks of 16B; swizzle within 128B halves
    auto load_stage = [&](int s) {
        __half* dA = As + (s & 1) * GA_ST;
        __half* dB = Bs + (s & 1) * GB_ST;
        const int kt = s * 128;
#pragma unroll
        for (int p = 0; p < 16; ++p) {
            const int idx = tid + p * 256;
            const int row = idx >> 4, c = idx & 15;
            const int pc = (c & 8) | ((c & 7) ^ (row & 7));
            cp16(dA + (row*16 + pc)*8, A + (size_t)(m0 + row) * HIDDEN + kt + c*8);
        }
#pragma unroll
        for (int p = 0; p < 8; ++p) {
            const int idx = tid + p * 256;
            const int row = idx >> 4, c = idx & 15;
            const int pc = (c & 8) | ((c & 7) ^ (row & 7));
            cp16(dB + (row*16 + pc)*8, W + (size_t)(n0 + row) * HIDDEN + kt + c*8);
        }
    };

    load_stage(0); cp_commit();

    const int a_rin  = lane & 15;
    const int a_koff = lane >> 4;
    const int b_nin  = (lane & 7) + ((lane >> 4) << 3);
    const int b_koff = (lane >> 3) & 1;

    for (int s = 0; s < NS; ++s) {
        if (s + 1 < NS) load_stage(s + 1);
        cp_commit();
        if (s + 1 < NS) cp_wait1(); else cp_wait0();
        __syncthreads();
        const __half* cA = As + (s & 1) * GA_ST;
        const __half* cB = Bs + (s & 1) * GB_ST;
#pragma unroll
        for (int ks = 0; ks < 8; ++ks) {
            unsigned a[4][4];
#pragma unroll
            for (int mi = 0; mi < 4; ++mi) {
                const int row = wr*64 + mi*16 + a_rin;
                const int ch  = ks*2 + a_koff;
                const int pc  = (ch & 8) | ((ch & 7) ^ (row & 7));
                ldsm4(a[mi], cA + (row*16 + pc)*8);
            }
            unsigned bf[8][2];
#pragma unroll
            for (int p = 0; p < 4; ++p) {
                const int row = wc*64 + p*16 + b_nin;
                const int ch  = ks*2 + b_koff;
                const int pc  = (ch & 8) | ((ch & 7) ^ (row & 7));
                unsigned q[4];
                ldsm4(q, cB + (row*16 + pc)*8);
                bf[2*p][0] = q[0]; bf[2*p][1] = q[1];
                bf[2*p+1][0] = q[2]; bf[2*p+1][1] = q[3];
            }
#pragma unroll
            for (int mi = 0; mi < 4; ++mi)
#pragma unroll
                for (int ni = 0; ni < 8; ++ni)
                    mma16816(acc[mi][ni], a[mi], bf[ni][0], bf[ni][1]);
        }
        __syncthreads();
    }

    // ---------------- epilogue ----------------
    if (mode == 0) {
        const int which = n0 / HIDDEN;
        __half* dst = (which == 0) ? g_qh : (which == 1) ? g_kh : g_vh;
#pragma unroll
        for (int mi = 0; mi < 4; ++mi)
#pragma unroll
            for (int ni = 0; ni < 8; ++ni) {
                const int col = n0 + wc*64 + ni*8 + 2*t;
                const int rem = col - which * HIDDEN;
                const int h   = rem / HD;
                const int d   = rem - h * HD;
                const float b0 = bias[col], b1 = bias[col + 1];
#pragma unroll
                for (int half_ = 0; half_ < 2; ++half_) {
                    const int row = m0 + wr*64 + mi*16 + g + half_*8;
                    const int bi  = row >> 10, si = row & (SEQ - 1);
                    __half2 v = __floats2half2_rn(acc[mi][ni][2*half_] + b0,
                                                  acc[mi][ni][2*half_+1] + b1);
                    *(__half2*)&dst[(((size_t)(bi*HEADS + h))*SEQ + si)*HD + d] = v;
                }
            }
    } else {
#pragma unroll
        for (int mi = 0; mi < 4; ++mi)
#pragma unroll
            for (int ni = 0; ni < 8; ++ni) {
                const int col = n0 + wc*64 + ni*8 + 2*t;
                const float b0 = bias[col], b1 = bias[col + 1];
#pragma unroll
                for (int half_ = 0; half_ < 2; ++half_) {
                    const int row = m0 + wr*64 + mi*16 + g + half_*8;
                    float2 v = make_float2(acc[mi][ni][2*half_] + b0,
                                           acc[mi][ni][2*half_+1] + b1);
                    *(float2*)&out[(size_t)row * HIDDEN + col] = v;
                }
            }
    }
}

// ---------------- RMSNorm (half in/out), scale folded ----------------
__global__ __launch_bounds__(256) void rmsnorm_h_kernel(__half* __restrict__ tp,
                                                        const float* __restrict__ gamma,
                                                        float scale) {
    const int row  = blockIdx.x * 8 + (threadIdx.x >> 5);
    const int lane = threadIdx.x & 31;
    __half* p = tp + (size_t)row * HD;
    float v0 = __half2float(p[lane]);
    float v1 = __half2float(p[32 + lane]);
    float v2 = (lane < 8) ? __half2float(p[64 + lane]) : 0.f;
    float ss = v0*v0 + v1*v1 + v2*v2;
#pragma unroll
    for (int o = 16; o; o >>= 1) ss += __shfl_xor_sync(0xffffffffu, ss, o);
    const float rs = rsqrtf(ss * (1.0f/72.0f) + RMS_EPS) * scale;
    p[lane]      = __float2half(v0 * rs * gamma[lane]);
    p[32 + lane] = __float2half(v1 * rs * gamma[32 + lane]);
    if (lane < 8) p[64 + lane] = __float2half(v2 * rs * gamma[64 + lane]);
}

// =======================================================================
// fp16 flash attention, NO online max (|score| <= sqrt(72) after RMSNorm).
// CTA = (b,h,128 q rows), 8 warps x 16 rows, K/V double-buffered.
// =======================================================================
#define AQ_H (128*80)
#define AK_H (2*64*80)
#define ATTN_SMEM ((AQ_H + 2*AK_H)*2)    // 61440 bytes

__global__ __launch_bounds__(256, 2) void attn_f16_kernel() {
    extern __shared__ __half asm_[];
    __half* Qs = asm_;
    __half* Ks = Qs + AQ_H;
    __half* Vs = Ks + AK_H;

    const int qt = blockIdx.x;
    const int h  = blockIdx.y;
    const int b  = blockIdx.z;
    const int tid  = threadIdx.x;
    const int warp = tid >> 5;
    const int lane = tid & 31;
    const int g    = lane >> 2;
    const int t    = lane & 3;

    const size_t head_base = ((size_t)(b*HEADS + h)) * SEQ * HD;
    const __half* gQ = g_qh + head_base + (size_t)qt * 128 * HD;
    const __half* gK = g_kh + head_base;
    const __half* gV = g_vh + head_base;

    for (int r = tid; r < 384; r += 256) {
        __half* base = (r < 128) ? Qs : (r < 256) ? Ks : Vs;
        const int rr = r & 127;
        *(uint4*)&base[(rr*10 + 9)*8] = make_uint4(0,0,0,0);
    }
    for (int idx = tid; idx < 1152; idx += 256) {
        const int row = idx / 9, c = idx - row*9;
        const int pc = (c < 8) ? (c ^ (row & 7)) : 8;
        cp16(Qs + (row*10 + pc)*8, gQ + row*HD + c*8);
    }
    auto load_kv = [&](int kt) {
        __half* Kb = Ks + (kt & 1) * 64*80;
        __half* Vb = Vs + (kt & 1) * 64*80;
        const size_t base = (size_t)kt * 64 * HD;
        for (int idx = tid; idx < 1152; idx += 256) {
            const int arr = idx >= 576;
            const int rem = idx - 576*arr;
            const int row = rem / 9, c = rem - row*9;
            const int pc = (c < 8) ? (c ^ (row & 7)) : 8;
            if (arr) cp16(Vb + (row*10 + pc)*8, gV + base + row*HD + c*8);
            else     cp16(Kb + (row*10 + pc)*8, gK + base + row*HD + c*8);
        }
    };
    load_kv(0);
    cp_commit();

    float o[9][4];
#pragma unroll
    for (int n = 0; n < 9; ++n)
#pragma unroll
        for (int r = 0; r < 4; ++r) o[n][r] = 0.f;
    float l0 = 0.f, l1 = 0.f;

    const int a_rin  = lane & 15;
    const int a_koff = lane >> 4;
    const int b_nin  = (lane & 7) + ((lane >> 4) << 3);
    const int b_koff = (lane >> 3) & 1;
    const int v_sin  = (lane & 7) + ((lane >> 3) & 1) * 8;
    const int v_doff = lane >> 4;

    for (int kt = 0; kt < SEQ/64; ++kt) {
        if (kt + 1 < SEQ/64) load_kv(kt + 1);
        cp_commit();
        cp_wait1();
        __syncthreads();
        const __half* Kb = Ks + (kt & 1) * 64*80;
        const __half* Vb = Vs + (kt & 1) * 64*80;

        // ---- S = Q @ K^T ----
        float c[8][4];
#pragma unroll
        for (int n = 0; n < 8; ++n)
#pragma unroll
            for (int r = 0; r < 4; ++r) c[n][r] = 0.f;
#pragma unroll
        for (int ks = 0; ks < 5; ++ks) {
            unsigned aq[4];
            {
                const int row = warp*16 + a_rin;
                const int ch  = 2*ks + a_koff;
                const int pc  = (ch < 8) ? (ch ^ (row & 7)) : ch;
                ldsm4(aq, Qs + (row*10 + pc)*8);
            }
#pragma unroll
            for (int p = 0; p < 4; ++p) {
                const int row = p*16 + b_nin;
                const int ch  = 2*ks + b_koff;
                const int pc  = (ch < 8) ? (ch ^ (row & 7)) : ch;
                unsigned q[4];
                ldsm4(q, Kb + (row*10 + pc)*8);
                mma16816(c[2*p],   aq, q[0], q[1]);
                mma16816(c[2*p+1], aq, q[2], q[3]);
            }
        }

        // ---- softmax, no max subtraction ----
        float sum0 = 0.f, sum1 = 0.f;
#pragma unroll
        for (int n = 0; n < 8; ++n) {
            c[n][0] = __expf(c[n][0]);
            c[n][1] = __expf(c[n][1]);
            c[n][2] = __expf(c[n][2]);
            c[n][3] = __expf(c[n][3]);
            sum0 += c[n][0] + c[n][1];
            sum1 += c[n][2] + c[n][3];
        }
        sum0 += __shfl_xor_sync(0xffffffffu, sum0, 1);
        sum0 += __shfl_xor_sync(0xffffffffu, sum0, 2);
        sum1 += __shfl_xor_sync(0xffffffffu, sum1, 1);
        sum1 += __shfl_xor_sync(0xffffffffu, sum1, 2);
        l0 += sum0;
        l1 += sum1;

        unsigned pa[4][4];
#pragma unroll
        for (int k2 = 0; k2 < 4; ++k2) {
            pa[k2][0] = h2u(__floats2half2_rn(c[2*k2][0],   c[2*k2][1]));
            pa[k2][1] = h2u(__floats2half2_rn(c[2*k2][2],   c[2*k2][3]));
            pa[k2][2] = h2u(__floats2half2_rn(c[2*k2+1][0], c[2*k2+1][1]));
            pa[k2][3] = h2u(__floats2half2_rn(c[2*k2+1][2], c[2*k2+1][3]));
        }

        // ---- O += P @ V ----
#pragma unroll
        for (int k2 = 0; k2 < 4; ++k2) {
#pragma unroll
            for (int p2 = 0; p2 < 4; ++p2) {
                const int srow = k2*16 + v_sin;
                const int ch   = 2*p2 + v_doff;
                const int pc   = ch ^ (srow & 7);
                unsigned q[4];
                ldsm4t(q, Vb + (srow*10 + pc)*8);
                mma16816(o[2*p2],   pa[k2], q[0], q[1]);
                mma16816(o[2*p2+1], pa[k2], q[2], q[3]);
            }
            {
                const int srow = k2*16 + v_sin;
                unsigned q2[2];
                ldsm2t(q2, Vb + (srow*10 + 8)*8);
                mma16816(o[8], pa[k2], q2[0], q2[1]);
            }
        }
        __syncthreads();
    }

    // ---- epilogue ----
    const float inv0 = 1.0f / l0, inv1 = 1.0f / l1;
    const int q0 = qt*128 + warp*16 + g;
    __half* base0 = g_ah + ((size_t)(b*SEQ + q0)     * HIDDEN) + h*HD;
    __half* base1 = g_ah + ((size_t)(b*SEQ + q0 + 8) * HIDDEN) + h*HD;
#pragma unroll
    for (int n = 0; n < 9; ++n) {
        const int d = n*8 + 2*t;
        *(__half2*)&base0[d] = __floats2half2_rn(o[n][0]*inv0, o[n][1]*inv0);
        *(__half2*)&base1[d] = __floats2half2_rn(o[n][2]*inv1, o[n][3]*inv1);
    }
}

// ---------------- launch ----------------
extern "C" void kernel_launch(void* const* d_in, const int* in_sizes, int n_in,
                              void* d_out, int out_size) {
    const float* x      = (const float*)d_in[0];
    const float* w_qkv  = (const float*)d_in[1];
    const float* b_qkv  = (const float*)d_in[2];
    const float* q_gamma= (const float*)d_in[3];
    const float* k_gamma= (const float*)d_in[4];
    const float* w_proj = (const float*)d_in[5];
    const float* b_proj = (const float*)d_in[6];
    float* out = (float*)d_out;

    cudaFuncSetAttribute(gemm_f16_kernel, cudaFuncAttributeMaxDynamicSharedMemorySize, GEMM_SMEM);
    cudaFuncSetAttribute(attn_f16_kernel, cudaFuncAttributeMaxDynamicSharedMemorySize, ATTN_SMEM);

    __half *xh, *wqh, *wph, *ah, *qh, *kh;
    cudaGetSymbolAddress((void**)&xh,  g_xh);
    cudaGetSymbolAddress((void**)&wqh, g_wqh);
    cudaGetSymbolAddress((void**)&wph, g_wph);
    cudaGetSymbolAddress((void**)&ah,  g_ah);
    cudaGetSymbolAddress((void**)&qh,  g_qh);
    cudaGetSymbolAddress((void**)&kh,  g_kh);

    {   // fp32 -> fp16 conversions
        int n8x = M_TOT*HIDDEN/8, n8q = N_QKV*HIDDEN/8, n8p = HIDDEN*HIDDEN/8;
        conv_h_kernel<<<(n8x+255)/256, 256>>>((const float4*)x, (uint4*)xh, n8x);
        conv_h_kernel<<<(n8q+255)/256, 256>>>((const float4*)w_qkv, (uint4*)wqh, n8q);
        conv_h_kernel<<<(n8p+255)/256, 256>>>((const float4*)w_proj, (uint4*)wph, n8p);
    }
    {   // QKV projection
        dim3 grid(N_QKV/128, M_TOT/256);   // (27, 64)
        gemm_f16_kernel<<<grid, 256, GEMM_SMEM>>>(xh, wqh, b_qkv, nullptr, 0);
    }
    {   // RMSNorm (q gets 1/sqrt(hd) folded in)
        const int rows = BATCH*HEADS*SEQ;
        rmsnorm_h_kernel<<<rows/8, 256>>>(qh, q_gamma, QSCALE);
        rmsnorm_h_kernel<<<rows/8, 256>>>(kh, k_gamma, 1.0f);
    }
    {   // attention
        dim3 grid(SEQ/128, HEADS, BATCH);  // (8,16,16)
        attn_f16_kernel<<<grid, 256, ATTN_SMEM>>>();
    }
    {   // output projection
        dim3 grid(HIDDEN/128, M_TOT/256);  // (9, 64)
        gemm_f16_kernel<<<grid, 256, GEMM_SMEM>>>(ah, wph, b_proj, out, 1);
    }
}

// round 8
// speedup vs baseline: 1.5722x; 1.0149x over previous
#include <cuda_runtime.h>
#include <cuda_fp16.h>
#include <math.h>

#define HIDDEN 1152
#define HEADS  16
#define HD     72
#define BATCH  16
#define SEQ    1024
#define M_TOT  (BATCH*SEQ)
#define N_QKV  (3*HIDDEN)
#define QSCALE 0.11785113f
#define RMS_EPS 1.1920928955078125e-07f

// ---------------- scratch ----------------
__device__ __align__(256) __half g_qh[(size_t)BATCH*HEADS*SEQ*HD];
__device__ __align__(256) __half g_kh[(size_t)BATCH*HEADS*SEQ*HD];
__device__ __align__(256) __half g_vh[(size_t)BATCH*HEADS*SEQ*HD];
__device__ __align__(256) __half g_ah[(size_t)M_TOT*HIDDEN];
__device__ __align__(256) __half g_xh[(size_t)M_TOT*HIDDEN];
__device__ __align__(256) __half g_wqh[(size_t)N_QKV*HIDDEN];
__device__ __align__(256) __half g_wph[(size_t)HIDDEN*HIDDEN];

// ---------------- helpers ----------------
__device__ __forceinline__ unsigned h2u(__half2 h) {
    unsigned u;
    asm("mov.b32 %0, %1;" : "=r"(u) : "r"(*(unsigned*)&h));
    return u;
}
__device__ __forceinline__ unsigned sptr(const void* p) {
    return (unsigned)__cvta_generic_to_shared(p);
}
__device__ __forceinline__ void ldsm4(unsigned r[4], const void* p) {
    asm volatile("ldmatrix.sync.aligned.m8n8.x4.shared.b16 {%0,%1,%2,%3},[%4];"
                 : "=r"(r[0]), "=r"(r[1]), "=r"(r[2]), "=r"(r[3]) : "r"(sptr(p)));
}
__device__ __forceinline__ void ldsm4t(unsigned r[4], const void* p) {
    asm volatile("ldmatrix.sync.aligned.m8n8.x4.trans.shared.b16 {%0,%1,%2,%3},[%4];"
                 : "=r"(r[0]), "=r"(r[1]), "=r"(r[2]), "=r"(r[3]) : "r"(sptr(p)));
}
__device__ __forceinline__ void ldsm2t(unsigned r[2], const void* p) {
    asm volatile("ldmatrix.sync.aligned.m8n8.x2.trans.shared.b16 {%0,%1},[%2];"
                 : "=r"(r[0]), "=r"(r[1]) : "r"(sptr(p)));
}
__device__ __forceinline__ void mma16816(float c[4], const unsigned a[4],
                                         unsigned b0, unsigned b1) {
    asm volatile(
        "mma.sync.aligned.m16n8k16.row.col.f32.f16.f16.f32 "
        "{%0,%1,%2,%3},{%4,%5,%6,%7},{%8,%9},{%0,%1,%2,%3};"
        : "+f"(c[0]), "+f"(c[1]), "+f"(c[2]), "+f"(c[3])
        : "r"(a[0]), "r"(a[1]), "r"(a[2]), "r"(a[3]), "r"(b0), "r"(b1));
}
__device__ __forceinline__ void cp16(void* smem, const void* g) {
    asm volatile("cp.async.ca.shared.global [%0], [%1], 16;" :: "r"(sptr(smem)), "l"(g));
}
__device__ __forceinline__ void cp_commit() { asm volatile("cp.async.commit_group;"); }
__device__ __forceinline__ void cp_wait0()  { asm volatile("cp.async.wait_group 0;"); }
__device__ __forceinline__ void cp_wait1()  { asm volatile("cp.async.wait_group 1;"); }
__device__ __forceinline__ void cp_wait2()  { asm volatile("cp.async.wait_group 2;"); }

// ---------------- fp32 -> fp16 conversion ----------------
__global__ __launch_bounds__(256) void conv_h_kernel(const float4* __restrict__ src,
                                                     uint4* __restrict__ dst, int n8) {
    int i = blockIdx.x * 256 + threadIdx.x;
    if (i < n8) {
        float4 f0 = src[2*i], f1 = src[2*i+1];
        uint4 o;
        o.x = h2u(__floats2half2_rn(f0.x, f0.y));
        o.y = h2u(__floats2half2_rn(f0.z, f0.w));
        o.z = h2u(__floats2half2_rn(f1.x, f1.y));
        o.w = h2u(__floats2half2_rn(f1.z, f1.w));
        dst[i] = o;
    }
}

// =======================================================================
// fp16 GEMM (R5 config): BM=256 BN=128 BK=64, 256 thr = 8 warps (4x2),
// warp tile 64x64, 3-stage cp.async, XOR-swizzled smem.
// =======================================================================
#define GA_ST 16384   // halves per A stage
#define GB_ST 8192    // halves per B stage
#define GEMM_SMEM (3*(GA_ST+GB_ST)*2)   // 147456 bytes

__global__ __launch_bounds__(256) void gemm_f16_kernel(const __half* __restrict__ A,
                                                       const __half* __restrict__ W,
                                                       const float* __restrict__ bias,
                                                       float* __restrict__ out,
                                                       int mode) {
    extern __shared__ __half hsm[];
    __half* As = hsm;
    __half* Bs = hsm + 3*GA_ST;

    const int tid  = threadIdx.x;
    const int warp = tid >> 5;
    const int wr   = warp >> 1;     // 0..3
    const int wc   = warp & 1;      // 0..1
    const int lane = tid & 31;
    const int g    = lane >> 2;
    const int t    = lane & 3;

    const int m0 = blockIdx.y * 256;
    const int n0 = blockIdx.x * 128;

    float acc[4][8][4];
#pragma unroll
    for (int mi = 0; mi < 4; ++mi)
#pragma unroll
        for (int ni = 0; ni < 8; ++ni)
#pragma unroll
            for (int r = 0; r < 4; ++r) acc[mi][ni][r] = 0.f;

    const int NS = HIDDEN / 64;   // 18

    auto load_stage = [&](int s) {
        __half* dA = As + (s % 3) * GA_ST;
        __half* dB = Bs + (s % 3) * GB_ST;
        const int kt = s * 64;
#pragma unroll
        for (int p = 0; p < 8; ++p) {
            const int idx = tid + p * 256;
            const int row = idx >> 3, c = idx & 7, pc = c ^ (row & 7);
            cp16(dA + (row*8 + pc)*8, A + (size_t)(m0 + row) * HIDDEN + kt + c*8);
        }
#pragma unroll
        for (int p = 0; p < 4; ++p) {
            const int idx = tid + p * 256;
            const int row = idx >> 3, c = idx & 7, pc = c ^ (row & 7);
            cp16(dB + (row*8 + pc)*8, W + (size_t)(n0 + row) * HIDDEN + kt + c*8);
        }
    };

    load_stage(0); cp_commit();
    load_stage(1); cp_commit();

    const int a_rin  = lane & 15;
    const int a_koff = lane >> 4;
    const int b_nin  = (lane & 7) + ((lane >> 4) << 3);
    const int b_koff = (lane >> 3) & 1;

    for (int s = 0; s < NS; ++s) {
        if (s + 2 < NS) load_stage(s + 2);
        cp_commit();
        cp_wait2();
        __syncthreads();
        const __half* cA = As + (s % 3) * GA_ST;
        const __half* cB = Bs + (s % 3) * GB_ST;
#pragma unroll
        for (int ks = 0; ks < 4; ++ks) {
            unsigned a[4][4];
#pragma unroll
            for (int mi = 0; mi < 4; ++mi) {
                const int row = wr*64 + mi*16 + a_rin;
                const int pc  = (ks*2 + a_koff) ^ (row & 7);
                ldsm4(a[mi], cA + (row*8 + pc)*8);
            }
            unsigned bf[8][2];
#pragma unroll
            for (int p = 0; p < 4; ++p) {
                const int row = wc*64 + p*16 + b_nin;
                const int pc  = (ks*2 + b_koff) ^ (row & 7);
                unsigned q[4];
                ldsm4(q, cB + (row*8 + pc)*8);
                bf[2*p][0] = q[0]; bf[2*p][1] = q[1];
                bf[2*p+1][0] = q[2]; bf[2*p+1][1] = q[3];
            }
#pragma unroll
            for (int mi = 0; mi < 4; ++mi)
#pragma unroll
                for (int ni = 0; ni < 8; ++ni)
                    mma16816(acc[mi][ni], a[mi], bf[ni][0], bf[ni][1]);
        }
        __syncthreads();
    }

    // ---------------- epilogue ----------------
    if (mode == 0) {
        const int which = n0 / HIDDEN;
        __half* dst = (which == 0) ? g_qh : (which == 1) ? g_kh : g_vh;
#pragma unroll
        for (int mi = 0; mi < 4; ++mi)
#pragma unroll
            for (int ni = 0; ni < 8; ++ni) {
                const int col = n0 + wc*64 + ni*8 + 2*t;
                const int rem = col - which * HIDDEN;
                const int h   = rem / HD;
                const int d   = rem - h * HD;
                const float b0 = bias[col], b1 = bias[col + 1];
#pragma unroll
                for (int half_ = 0; half_ < 2; ++half_) {
                    const int row = m0 + wr*64 + mi*16 + g + half_*8;
                    const int bi  = row >> 10, si = row & (SEQ - 1);
                    __half2 v = __floats2half2_rn(acc[mi][ni][2*half_] + b0,
                                                  acc[mi][ni][2*half_+1] + b1);
                    *(__half2*)&dst[(((size_t)(bi*HEADS + h))*SEQ + si)*HD + d] = v;
                }
            }
    } else {
#pragma unroll
        for (int mi = 0; mi < 4; ++mi)
#pragma unroll
            for (int ni = 0; ni < 8; ++ni) {
                const int col = n0 + wc*64 + ni*8 + 2*t;
                const float b0 = bias[col], b1 = bias[col + 1];
#pragma unroll
                for (int half_ = 0; half_ < 2; ++half_) {
                    const int row = m0 + wr*64 + mi*16 + g + half_*8;
                    float2 v = make_float2(acc[mi][ni][2*half_] + b0,
                                           acc[mi][ni][2*half_+1] + b1);
                    *(float2*)&out[(size_t)row * HIDDEN + col] = v;
                }
            }
    }
}

// ---------------- fused RMSNorm: blockIdx.y 0 -> q (scaled), 1 -> k ----------------
__global__ __launch_bounds__(256) void rmsnorm_h_kernel(const float* __restrict__ q_gamma,
                                                        const float* __restrict__ k_gamma) {
    __half* tp = blockIdx.y ? g_kh : g_qh;
    const float* gamma = blockIdx.y ? k_gamma : q_gamma;
    const float scale = blockIdx.y ? 1.0f : QSCALE;
    const int row  = blockIdx.x * 8 + (threadIdx.x >> 5);
    const int lane = threadIdx.x & 31;
    __half* p = tp + (size_t)row * HD;
    float v0 = __half2float(p[lane]);
    float v1 = __half2float(p[32 + lane]);
    float v2 = (lane < 8) ? __half2float(p[64 + lane]) : 0.f;
    float ss = v0*v0 + v1*v1 + v2*v2;
#pragma unroll
    for (int o = 16; o; o >>= 1) ss += __shfl_xor_sync(0xffffffffu, ss, o);
    const float rs = rsqrtf(ss * (1.0f/72.0f) + RMS_EPS) * scale;
    p[lane]      = __float2half(v0 * rs * gamma[lane]);
    p[32 + lane] = __float2half(v1 * rs * gamma[32 + lane]);
    if (lane < 8) p[64 + lane] = __float2half(v2 * rs * gamma[64 + lane]);
}

// =======================================================================
// fp16 flash attention, NO online max (|score| <= sqrt(72) after RMSNorm).
// CTA = (b,h,128 q rows), 8 warps x 16 rows, 3-stage KV ring,
// ONE __syncthreads per KV iteration.
// =======================================================================
#define AQ_H (128*80)
#define AKV1 (64*80)
#define ATTN_SMEM ((AQ_H + 6*AKV1)*2)    // 81920 bytes -> 2 CTA/SM

__global__ __launch_bounds__(256, 2) void attn_f16_kernel() {
    extern __shared__ __half asm_[];
    __half* Qs = asm_;                 // 128 x 80
    __half* Ks = Qs + AQ_H;            // 3 x 64 x 80
    __half* Vs = Ks + 3*AKV1;          // 3 x 64 x 80

    const int qt = blockIdx.x;
    const int h  = blockIdx.y;
    const int b  = blockIdx.z;
    const int tid  = threadIdx.x;
    const int warp = tid >> 5;
    const int lane = tid & 31;
    const int g    = lane >> 2;
    const int t    = lane & 3;

    const size_t head_base = ((size_t)(b*HEADS + h)) * SEQ * HD;
    const __half* gQ = g_qh + head_base + (size_t)qt * 128 * HD;
    const __half* gK = g_kh + head_base;
    const __half* gV = g_vh + head_base;

    // zero pad chunk 9 of every row: Q 128 rows + K 192 + V 192 = 512
    for (int r = tid; r < 512; r += 256) {
        __half* base;
        int rr;
        if (r < 128)      { base = Qs; rr = r; }
        else if (r < 320) { base = Ks; rr = r - 128; }
        else              { base = Vs; rr = r - 320; }
        *(uint4*)&base[(rr*10 + 9)*8] = make_uint4(0,0,0,0);
    }

    auto load_kv = [&](int kt) {
        __half* Kb = Ks + (kt % 3) * AKV1;
        __half* Vb = Vs + (kt % 3) * AKV1;
        const size_t base = (size_t)kt * 64 * HD;
        for (int idx = tid; idx < 1152; idx += 256) {
            const int arr = idx >= 576;
            const int rem = idx - 576*arr;
            const int row = rem / 9, c = rem - row*9;
            const int pc = (c < 8) ? (c ^ (row & 7)) : 8;
            if (arr) cp16(Vb + (row*10 + pc)*8, gV + base + row*HD + c*8);
            else     cp16(Kb + (row*10 + pc)*8, gK + base + row*HD + c*8);
        }
    };

    // group 0: Q + KV tile 0; group 1: KV tile 1
    for (int idx = tid; idx < 1152; idx += 256) {
        const int row = idx / 9, c = idx - row*9;
        const int pc = (c < 8) ? (c ^ (row & 7)) : 8;
        cp16(Qs + (row*10 + pc)*8, gQ + row*HD + c*8);
    }
    load_kv(0);
    cp_commit();
    load_kv(1);
    cp_commit();

    float o[9][4];
#pragma unroll
    for (int n = 0; n < 9; ++n)
#pragma unroll
        for (int r = 0; r < 4; ++r) o[n][r] = 0.f;
    float l0 = 0.f, l1 = 0.f;

    const int a_rin  = lane & 15;
    const int a_koff = lane >> 4;
    const int b_nin  = (lane & 7) + ((lane >> 4) << 3);
    const int b_koff = (lane >> 3) & 1;
    const int v_sin  = (lane & 7) + ((lane >> 3) & 1) * 8;
    const int v_doff = lane >> 4;

    const int KT = SEQ / 64;   // 16

    for (int kt = 0; kt < KT; ++kt) {
        // loads(kt) done (leave loads(kt+1) pending)
        if (kt == KT - 1) cp_wait0(); else cp_wait1();
        __syncthreads();   // all warps finished reading buffer (kt+2)%3 (used at kt-1)
        if (kt + 2 < KT) { load_kv(kt + 2); cp_commit(); }

        const __half* Kb = Ks + (kt % 3) * AKV1;
        const __half* Vb = Vs + (kt % 3) * AKV1;

        // ---- S = Q @ K^T ----
        float c[8][4];
#pragma unroll
        for (int n = 0; n < 8; ++n)
#pragma unroll
            for (int r = 0; r < 4; ++r) c[n][r] = 0.f;
#pragma unroll
        for (int ks = 0; ks < 5; ++ks) {
            unsigned aq[4];
            {
                const int row = warp*16 + a_rin;
                const int ch  = 2*ks + a_koff;
                const int pc  = (ch < 8) ? (ch ^ (row & 7)) : ch;
                ldsm4(aq, Qs + (row*10 + pc)*8);
            }
#pragma unroll
            for (int p = 0; p < 4; ++p) {
                const int row = p*16 + b_nin;
                const int ch  = 2*ks + b_koff;
                const int pc  = (ch < 8) ? (ch ^ (row & 7)) : ch;
                unsigned q[4];
                ldsm4(q, Kb + (row*10 + pc)*8);
                mma16816(c[2*p],   aq, q[0], q[1]);
                mma16816(c[2*p+1], aq, q[2], q[3]);
            }
        }

        // ---- softmax, no max subtraction ----
        float sum0 = 0.f, sum1 = 0.f;
#pragma unroll
        for (int n = 0; n < 8; ++n) {
            c[n][0] = __expf(c[n][0]);
            c[n][1] = __expf(c[n][1]);
            c[n][2] = __expf(c[n][2]);
            c[n][3] = __expf(c[n][3]);
            sum0 += c[n][0] + c[n][1];
            sum1 += c[n][2] + c[n][3];
        }
        sum0 += __shfl_xor_sync(0xffffffffu, sum0, 1);
        sum0 += __shfl_xor_sync(0xffffffffu, sum0, 2);
        sum1 += __shfl_xor_sync(0xffffffffu, sum1, 1);
        sum1 += __shfl_xor_sync(0xffffffffu, sum1, 2);
        l0 += sum0;
        l1 += sum1;

        unsigned pa[4][4];
#pragma unroll
        for (int k2 = 0; k2 < 4; ++k2) {
            pa[k2][0] = h2u(__floats2half2_rn(c[2*k2][0],   c[2*k2][1]));
            pa[k2][1] = h2u(__floats2half2_rn(c[2*k2][2],   c[2*k2][3]));
            pa[k2][2] = h2u(__floats2half2_rn(c[2*k2+1][0], c[2*k2+1][1]));
            pa[k2][3] = h2u(__floats2half2_rn(c[2*k2+1][2], c[2*k2+1][3]));
        }

        // ---- O += P @ V ----
#pragma unroll
        for (int k2 = 0; k2 < 4; ++k2) {
#pragma unroll
            for (int p2 = 0; p2 < 4; ++p2) {
                const int srow = k2*16 + v_sin;
                const int ch   = 2*p2 + v_doff;
                const int pc   = ch ^ (srow & 7);
                unsigned q[4];
                ldsm4t(q, Vb + (srow*10 + pc)*8);
                mma16816(o[2*p2],   pa[k2], q[0], q[1]);
                mma16816(o[2*p2+1], pa[k2], q[2], q[3]);
            }
            {
                const int srow = k2*16 + v_sin;
                unsigned q2[2];
                ldsm2t(q2, Vb + (srow*10 + 8)*8);
                mma16816(o[8], pa[k2], q2[0], q2[1]);
            }
        }
    }

    // ---- epilogue ----
    const float inv0 = 1.0f / l0, inv1 = 1.0f / l1;
    const int q0 = qt*128 + warp*16 + g;
    __half* base0 = g_ah + ((size_t)(b*SEQ + q0)     * HIDDEN) + h*HD;
    __half* base1 = g_ah + ((size_t)(b*SEQ + q0 + 8) * HIDDEN) + h*HD;
#pragma unroll
    for (int n = 0; n < 9; ++n) {
        const int d = n*8 + 2*t;
        *(__half2*)&base0[d] = __floats2half2_rn(o[n][0]*inv0, o[n][1]*inv0);
        *(__half2*)&base1[d] = __floats2half2_rn(o[n][2]*inv1, o[n][3]*inv1);
    }
}

// ---------------- launch ----------------
extern "C" void kernel_launch(void* const* d_in, const int* in_sizes, int n_in,
                              void* d_out, int out_size) {
    const float* x      = (const float*)d_in[0];
    const float* w_qkv  = (const float*)d_in[1];
    const float* b_qkv  = (const float*)d_in[2];
    const float* q_gamma= (const float*)d_in[3];
    const float* k_gamma= (const float*)d_in[4];
    const float* w_proj = (const float*)d_in[5];
    const float* b_proj = (const float*)d_in[6];
    float* out = (float*)d_out;

    cudaFuncSetAttribute(gemm_f16_kernel, cudaFuncAttributeMaxDynamicSharedMemorySize, GEMM_SMEM);
    cudaFuncSetAttribute(attn_f16_kernel, cudaFuncAttributeMaxDynamicSharedMemorySize, ATTN_SMEM);

    __half *xh, *wqh, *wph, *ah;
    cudaGetSymbolAddress((void**)&xh,  g_xh);
    cudaGetSymbolAddress((void**)&wqh, g_wqh);
    cudaGetSymbolAddress((void**)&wph, g_wph);
    cudaGetSymbolAddress((void**)&ah,  g_ah);

    {   // fp32 -> fp16 conversions
        int n8x = M_TOT*HIDDEN/8, n8q = N_QKV*HIDDEN/8, n8p = HIDDEN*HIDDEN/8;
        conv_h_kernel<<<(n8x+255)/256, 256>>>((const float4*)x, (uint4*)xh, n8x);
        conv_h_kernel<<<(n8q+255)/256, 256>>>((const float4*)w_qkv, (uint4*)wqh, n8q);
        conv_h_kernel<<<(n8p+255)/256, 256>>>((const float4*)w_proj, (uint4*)wph, n8p);
    }
    {   // QKV projection
        dim3 grid(N_QKV/128, M_TOT/256);   // (27, 64)
        gemm_f16_kernel<<<grid, 256, GEMM_SMEM>>>(xh, wqh, b_qkv, nullptr, 0);
    }
    {   // fused RMSNorm (q + k in one launch)
        dim3 grid(BATCH*HEADS*SEQ/8, 2);
        rmsnorm_h_kernel<<<grid, 256>>>(q_gamma, k_gamma);
    }
    {   // attention
        dim3 grid(SEQ/128, HEADS, BATCH);  // (8,16,16)
        attn_f16_kernel<<<grid, 256, ATTN_SMEM>>>();
    }
    {   // output projection
        dim3 grid(HIDDEN/128, M_TOT/256);  // (9, 64)
        gemm_f16_kernel<<<grid, 256, GEMM_SMEM>>>(ah, wph, b_proj, out, 1);
    }
}

// round 9
// speedup vs baseline: 1.6405x; 1.0435x over previous
#include <cuda_runtime.h>
#include <cuda.h>
#include <cuda_fp16.h>
#include <math.h>

#define HIDDEN 1152
#define HEADS  16
#define HD     72
#define BATCH  16
#define SEQ    1024
#define M_TOT  (BATCH*SEQ)
#define N_QKV  (3*HIDDEN)
#define QSCALE 0.11785113f
#define RMS_EPS 1.1920928955078125e-07f

// ---------------- scratch ----------------
__device__ __align__(256) __half g_qh[(size_t)BATCH*HEADS*SEQ*HD];
__device__ __align__(256) __half g_kh[(size_t)BATCH*HEADS*SEQ*HD];
__device__ __align__(256) __half g_vh[(size_t)BATCH*HEADS*SEQ*HD];
__device__ __align__(256) __half g_ah[(size_t)M_TOT*HIDDEN];
__device__ __align__(256) __half g_xh[(size_t)M_TOT*HIDDEN];
__device__ __align__(256) __half g_wqh[(size_t)N_QKV*HIDDEN];
__device__ __align__(256) __half g_wph[(size_t)HIDDEN*HIDDEN];

// ---------------- helpers ----------------
__device__ __forceinline__ unsigned h2u(__half2 h) {
    unsigned u;
    asm("mov.b32 %0, %1;" : "=r"(u) : "r"(*(unsigned*)&h));
    return u;
}
__device__ __forceinline__ unsigned sptr(const void* p) {
    return (unsigned)__cvta_generic_to_shared(p);
}
__device__ __forceinline__ void ldsm4(unsigned r[4], const void* p) {
    asm volatile("ldmatrix.sync.aligned.m8n8.x4.shared.b16 {%0,%1,%2,%3},[%4];"
                 : "=r"(r[0]), "=r"(r[1]), "=r"(r[2]), "=r"(r[3]) : "r"(sptr(p)));
}
__device__ __forceinline__ void ldsm4t(unsigned r[4], const void* p) {
    asm volatile("ldmatrix.sync.aligned.m8n8.x4.trans.shared.b16 {%0,%1,%2,%3},[%4];"
                 : "=r"(r[0]), "=r"(r[1]), "=r"(r[2]), "=r"(r[3]) : "r"(sptr(p)));
}
__device__ __forceinline__ void ldsm2t(unsigned r[2], const void* p) {
    asm volatile("ldmatrix.sync.aligned.m8n8.x2.trans.shared.b16 {%0,%1},[%2];"
                 : "=r"(r[0]), "=r"(r[1]) : "r"(sptr(p)));
}
__device__ __forceinline__ void mma16816(float c[4], const unsigned a[4],
                                         unsigned b0, unsigned b1) {
    asm volatile(
        "mma.sync.aligned.m16n8k16.row.col.f32.f16.f16.f32 "
        "{%0,%1,%2,%3},{%4,%5,%6,%7},{%8,%9},{%0,%1,%2,%3};"
        : "+f"(c[0]), "+f"(c[1]), "+f"(c[2]), "+f"(c[3])
        : "r"(a[0]), "r"(a[1]), "r"(a[2]), "r"(a[3]), "r"(b0), "r"(b1));
}
__device__ __forceinline__ void cp16(void* smem, const void* g) {
    asm volatile("cp.async.ca.shared.global [%0], [%1], 16;" :: "r"(sptr(smem)), "l"(g));
}
__device__ __forceinline__ void cp_commit() { asm volatile("cp.async.commit_group;"); }
__device__ __forceinline__ void cp_wait0()  { asm volatile("cp.async.wait_group 0;"); }
__device__ __forceinline__ void cp_wait1()  { asm volatile("cp.async.wait_group 1;"); }

__device__ __forceinline__ void mbar_init(unsigned mbar, unsigned count) {
    asm volatile("mbarrier.init.shared.b64 [%0], %1;" :: "r"(mbar), "r"(count) : "memory");
}
__device__ __forceinline__ void mbar_expect_tx(unsigned mbar, unsigned bytes) {
    asm volatile("mbarrier.arrive.expect_tx.shared::cta.b64 _, [%0], %1;"
                 :: "r"(mbar), "r"(bytes) : "memory");
}
__device__ __forceinline__ void mbar_wait(unsigned mbar, unsigned parity) {
    asm volatile(
        "{\n\t.reg .pred P;\n\t"
        "LW%=: mbarrier.try_wait.parity.acquire.cta.shared::cta.b64 P, [%0], %1, 0x989680;\n\t"
        "@P bra LD%=;\n\t"
        "bra LW%=;\n\t"
        "LD%=:\n\t}"
        :: "r"(mbar), "r"(parity) : "memory");
}
__device__ __forceinline__ void tma2d(unsigned smem, const CUtensorMap* m,
                                      int cx, int cy, unsigned mbar) {
    asm volatile(
        "cp.async.bulk.tensor.2d.shared::cta.global.tile.mbarrier::complete_tx::bytes "
        "[%0], [%1, {%2, %3}], [%4];"
        :: "r"(smem), "l"(m), "r"(cx), "r"(cy), "r"(mbar) : "memory");
}

// ---------------- fp32 -> fp16 conversion ----------------
__global__ __launch_bounds__(256) void conv_h_kernel(const float4* __restrict__ src,
                                                     uint4* __restrict__ dst, int n8) {
    int i = blockIdx.x * 256 + threadIdx.x;
    if (i < n8) {
        float4 f0 = src[2*i], f1 = src[2*i+1];
        uint4 o;
        o.x = h2u(__floats2half2_rn(f0.x, f0.y));
        o.y = h2u(__floats2half2_rn(f0.z, f0.w));
        o.z = h2u(__floats2half2_rn(f1.x, f1.y));
        o.w = h2u(__floats2half2_rn(f1.z, f1.w));
        dst[i] = o;
    }
}

// =======================================================================
// fp16 GEMM, TMA-fed: BM=256 BN=128 BK=64, 256 thr = 8 warps (4x2),
// warp tile 64x64, 3-slot mbarrier ring, TMA SW128 (== XOR swizzle).
// =======================================================================
#define GA_ST 16384   // halves per A stage (256 rows x 64)
#define GB_ST 8192    // halves per B stage (128 rows x 64)
#define STAGE_BYTES ((GA_ST+GB_ST)*2)          // 49152
#define GEMM_SMEM (3*STAGE_BYTES + 64)         // + mbarriers

__global__ __launch_bounds__(256) void gemm_f16_kernel(
        const __grid_constant__ CUtensorMap mA,
        const __grid_constant__ CUtensorMap mB,
        const float* __restrict__ bias,
        float* __restrict__ out, int mode) {
    extern __shared__ __half hsm[];
    __half* As = hsm;                       // 3 x GA_ST
    __half* Bs = hsm + 3*GA_ST;             // 3 x GB_ST
    const unsigned mb = sptr(hsm) + 3*STAGE_BYTES;

    const int tid  = threadIdx.x;
    const int warp = tid >> 5;
    const int wr   = warp >> 1;     // 0..3
    const int wc   = warp & 1;      // 0..1
    const int lane = tid & 31;
    const int g    = lane >> 2;
    const int t    = lane & 3;

    const int m0 = blockIdx.y * 256;
    const int n0 = blockIdx.x * 128;

    float acc[4][8][4];
#pragma unroll
    for (int mi = 0; mi < 4; ++mi)
#pragma unroll
        for (int ni = 0; ni < 8; ++ni)
#pragma unroll
            for (int r = 0; r < 4; ++r) acc[mi][ni][r] = 0.f;

    const int NS = HIDDEN / 64;   // 18

    auto issue_load = [&](int s) {
        const int slot = s % 3;
        const unsigned full = mb + slot*8;
        mbar_expect_tx(full, STAGE_BYTES);
        tma2d(sptr(As + slot*GA_ST), &mA, s*64, m0, full);
        tma2d(sptr(Bs + slot*GB_ST), &mB, s*64, n0, full);
    };

    if (tid == 0) {
        mbar_init(mb,      1);
        mbar_init(mb + 8,  1);
        mbar_init(mb + 16, 1);
    }
    __syncthreads();
    if (tid == 0) { issue_load(0); issue_load(1); issue_load(2); }

    const int a_rin  = lane & 15;
    const int a_koff = lane >> 4;
    const int b_nin  = (lane & 7) + ((lane >> 4) << 3);
    const int b_koff = (lane >> 3) & 1;

    for (int s = 0; s < NS; ++s) {
        mbar_wait(mb + (s % 3)*8, (s / 3) & 1);
        const __half* cA = As + (s % 3) * GA_ST;
        const __half* cB = Bs + (s % 3) * GB_ST;
#pragma unroll
        for (int ks = 0; ks < 4; ++ks) {
            unsigned a[4][4];
#pragma unroll
            for (int mi = 0; mi < 4; ++mi) {
                const int row = wr*64 + mi*16 + a_rin;
                const int pc  = (ks*2 + a_koff) ^ (row & 7);
                ldsm4(a[mi], cA + (row*8 + pc)*8);
            }
            unsigned bf[8][2];
#pragma unroll
            for (int p = 0; p < 4; ++p) {
                const int row = wc*64 + p*16 + b_nin;
                const int pc  = (ks*2 + b_koff) ^ (row & 7);
                unsigned q[4];
                ldsm4(q, cB + (row*8 + pc)*8);
                bf[2*p][0] = q[0]; bf[2*p][1] = q[1];
                bf[2*p+1][0] = q[2]; bf[2*p+1][1] = q[3];
            }
#pragma unroll
            for (int mi = 0; mi < 4; ++mi)
#pragma unroll
                for (int ni = 0; ni < 8; ++ni)
                    mma16816(acc[mi][ni], a[mi], bf[ni][0], bf[ni][1]);
        }
        __syncthreads();   // all warps done with this slot
        if (s + 3 < NS && tid == 0) issue_load(s + 3);
    }

    // ---------------- epilogue ----------------
    if (mode == 0) {
        const int which = n0 / HIDDEN;
        __half* dst = (which == 0) ? g_qh : (which == 1) ? g_kh : g_vh;
#pragma unroll
        for (int mi = 0; mi < 4; ++mi)
#pragma unroll
            for (int ni = 0; ni < 8; ++ni) {
                const int col = n0 + wc*64 + ni*8 + 2*t;
                const int rem = col - which * HIDDEN;
                const int h   = rem / HD;
                const int d   = rem - h * HD;
                const float b0 = bias[col], b1 = bias[col + 1];
#pragma unroll
                for (int half_ = 0; half_ < 2; ++half_) {
                    const int row = m0 + wr*64 + mi*16 + g + half_*8;
                    const int bi  = row >> 10, si = row & (SEQ - 1);
                    __half2 v = __floats2half2_rn(acc[mi][ni][2*half_] + b0,
                                                  acc[mi][ni][2*half_+1] + b1);
                    *(__half2*)&dst[(((size_t)(bi*HEADS + h))*SEQ + si)*HD + d] = v;
                }
            }
    } else {
#pragma unroll
        for (int mi = 0; mi < 4; ++mi)
#pragma unroll
            for (int ni = 0; ni < 8; ++ni) {
                const int col = n0 + wc*64 + ni*8 + 2*t;
                const float b0 = bias[col], b1 = bias[col + 1];
#pragma unroll
                for (int half_ = 0; half_ < 2; ++half_) {
                    const int row = m0 + wr*64 + mi*16 + g + half_*8;
                    float2 v = make_float2(acc[mi][ni][2*half_] + b0,
                                           acc[mi][ni][2*half_+1] + b1);
                    *(float2*)&out[(size_t)row * HIDDEN + col] = v;
                }
            }
    }
}

// ---------------- fused RMSNorm: blockIdx.y 0 -> q (scaled), 1 -> k ----------------
__global__ __launch_bounds__(256) void rmsnorm_h_kernel(const float* __restrict__ q_gamma,
                                                        const float* __restrict__ k_gamma) {
    __half* tp = blockIdx.y ? g_kh : g_qh;
    const float* gamma = blockIdx.y ? k_gamma : q_gamma;
    const float scale = blockIdx.y ? 1.0f : QSCALE;
    const int row  = blockIdx.x * 8 + (threadIdx.x >> 5);
    const int lane = threadIdx.x & 31;
    __half* p = tp + (size_t)row * HD;
    float v0 = __half2float(p[lane]);
    float v1 = __half2float(p[32 + lane]);
    float v2 = (lane < 8) ? __half2float(p[64 + lane]) : 0.f;
    float ss = v0*v0 + v1*v1 + v2*v2;
#pragma unroll
    for (int o = 16; o; o >>= 1) ss += __shfl_xor_sync(0xffffffffu, ss, o);
    const float rs = rsqrtf(ss * (1.0f/72.0f) + RMS_EPS) * scale;
    p[lane]      = __float2half(v0 * rs * gamma[lane]);
    p[32 + lane] = __float2half(v1 * rs * gamma[32 + lane]);
    if (lane < 8) p[64 + lane] = __float2half(v2 * rs * gamma[64 + lane]);
}

// =======================================================================
// fp16 flash attention (R8): NO online max, 3-stage KV ring, one sync/iter.
// =======================================================================
#define AQ_H (128*80)
#define AKV1 (64*80)
#define ATTN_SMEM ((AQ_H + 6*AKV1)*2)    // 81920 bytes

__global__ __launch_bounds__(256, 2) void attn_f16_kernel() {
    extern __shared__ __half asm_[];
    __half* Qs = asm_;
    __half* Ks = Qs + AQ_H;
    __half* Vs = Ks + 3*AKV1;

    const int qt = blockIdx.x;
    const int h  = blockIdx.y;
    const int b  = blockIdx.z;
    const int tid  = threadIdx.x;
    const int warp = tid >> 5;
    const int lane = tid & 31;
    const int g    = lane >> 2;
    const int t    = lane & 3;

    const size_t head_base = ((size_t)(b*HEADS + h)) * SEQ * HD;
    const __half* gQ = g_qh + head_base + (size_t)qt * 128 * HD;
    const __half* gK = g_kh + head_base;
    const __half* gV = g_vh + head_base;

    for (int r = tid; r < 512; r += 256) {
        __half* base;
        int rr;
        if (r < 128)      { base = Qs; rr = r; }
        else if (r < 320) { base = Ks; rr = r - 128; }
        else              { base = Vs; rr = r - 320; }
        *(uint4*)&base[(rr*10 + 9)*8] = make_uint4(0,0,0,0);
    }

    auto load_kv = [&](int kt) {
        __half* Kb = Ks + (kt % 3) * AKV1;
        __half* Vb = Vs + (kt % 3) * AKV1;
        const size_t base = (size_t)kt * 64 * HD;
        for (int idx = tid; idx < 1152; idx += 256) {
            const int arr = idx >= 576;
            const int rem = idx - 576*arr;
            const int row = rem / 9, c = rem - row*9;
            const int pc = (c < 8) ? (c ^ (row & 7)) : 8;
            if (arr) cp16(Vb + (row*10 + pc)*8, gV + base + row*HD + c*8);
            else     cp16(Kb + (row*10 + pc)*8, gK + base + row*HD + c*8);
        }
    };

    for (int idx = tid; idx < 1152; idx += 256) {
        const int row = idx / 9, c = idx - row*9;
        const int pc = (c < 8) ? (c ^ (row & 7)) : 8;
        cp16(Qs + (row*10 + pc)*8, gQ + row*HD + c*8);
    }
    load_kv(0);
    cp_commit();
    load_kv(1);
    cp_commit();

    float o[9][4];
#pragma unroll
    for (int n = 0; n < 9; ++n)
#pragma unroll
        for (int r = 0; r < 4; ++r) o[n][r] = 0.f;
    float l0 = 0.f, l1 = 0.f;

    const int a_rin  = lane & 15;
    const int a_koff = lane >> 4;
    const int b_nin  = (lane & 7) + ((lane >> 4) << 3);
    const int b_koff = (lane >> 3) & 1;
    const int v_sin  = (lane & 7) + ((lane >> 3) & 1) * 8;
    const int v_doff = lane >> 4;

    const int KT = SEQ / 64;   // 16

    for (int kt = 0; kt < KT; ++kt) {
        if (kt == KT - 1) cp_wait0(); else cp_wait1();
        __syncthreads();
        if (kt + 2 < KT) { load_kv(kt + 2); cp_commit(); }

        const __half* Kb = Ks + (kt % 3) * AKV1;
        const __half* Vb = Vs + (kt % 3) * AKV1;

        float c[8][4];
#pragma unroll
        for (int n = 0; n < 8; ++n)
#pragma unroll
            for (int r = 0; r < 4; ++r) c[n][r] = 0.f;
#pragma unroll
        for (int ks = 0; ks < 5; ++ks) {
            unsigned aq[4];
            {
                const int row = warp*16 + a_rin;
                const int ch  = 2*ks + a_koff;
                const int pc  = (ch < 8) ? (ch ^ (row & 7)) : ch;
                ldsm4(aq, Qs + (row*10 + pc)*8);
            }
#pragma unroll
            for (int p = 0; p < 4; ++p) {
                const int row = p*16 + b_nin;
                const int ch  = 2*ks + b_koff;
                const int pc  = (ch < 8) ? (ch ^ (row & 7)) : ch;
                unsigned q[4];
                ldsm4(q, Kb + (row*10 + pc)*8);
                mma16816(c[2*p],   aq, q[0], q[1]);
                mma16816(c[2*p+1], aq, q[2], q[3]);
            }
        }

        float sum0 = 0.f, sum1 = 0.f;
#pragma unroll
        for (int n = 0; n < 8; ++n) {
            c[n][0] = __expf(c[n][0]);
            c[n][1] = __expf(c[n][1]);
            c[n][2] = __expf(c[n][2]);
            c[n][3] = __expf(c[n][3]);
            sum0 += c[n][0] + c[n][1];
            sum1 += c[n][2] + c[n][3];
        }
        sum0 += __shfl_xor_sync(0xffffffffu, sum0, 1);
        sum0 += __shfl_xor_sync(0xffffffffu, sum0, 2);
        sum1 += __shfl_xor_sync(0xffffffffu, sum1, 1);
        sum1 += __shfl_xor_sync(0xffffffffu, sum1, 2);
        l0 += sum0;
        l1 += sum1;

        unsigned pa[4][4];
#pragma unroll
        for (int k2 = 0; k2 < 4; ++k2) {
            pa[k2][0] = h2u(__floats2half2_rn(c[2*k2][0],   c[2*k2][1]));
            pa[k2][1] = h2u(__floats2half2_rn(c[2*k2][2],   c[2*k2][3]));
            pa[k2][2] = h2u(__floats2half2_rn(c[2*k2+1][0], c[2*k2+1][1]));
            pa[k2][3] = h2u(__floats2half2_rn(c[2*k2+1][2], c[2*k2+1][3]));
        }

#pragma unroll
        for (int k2 = 0; k2 < 4; ++k2) {
#pragma unroll
            for (int p2 = 0; p2 < 4; ++p2) {
                const int srow = k2*16 + v_sin;
                const int ch   = 2*p2 + v_doff;
                const int pc   = ch ^ (srow & 7);
                unsigned q[4];
                ldsm4t(q, Vb + (srow*10 + pc)*8);
                mma16816(o[2*p2],   pa[k2], q[0], q[1]);
                mma16816(o[2*p2+1], pa[k2], q[2], q[3]);
            }
            {
                const int srow = k2*16 + v_sin;
                unsigned q2[2];
                ldsm2t(q2, Vb + (srow*10 + 8)*8);
                mma16816(o[8], pa[k2], q2[0], q2[1]);
            }
        }
    }

    const float inv0 = 1.0f / l0, inv1 = 1.0f / l1;
    const int q0 = qt*128 + warp*16 + g;
    __half* base0 = g_ah + ((size_t)(b*SEQ + q0)     * HIDDEN) + h*HD;
    __half* base1 = g_ah + ((size_t)(b*SEQ + q0 + 8) * HIDDEN) + h*HD;
#pragma unroll
    for (int n = 0; n < 9; ++n) {
        const int d = n*8 + 2*t;
        *(__half2*)&base0[d] = __floats2half2_rn(o[n][0]*inv0, o[n][1]*inv0);
        *(__half2*)&base1[d] = __floats2half2_rn(o[n][2]*inv1, o[n][3]*inv1);
    }
}

// ---------------- host: tensor-map encode via driver entry point ----------------
typedef CUresult (*PFN_tmeTiled_v12)(CUtensorMap*, CUtensorMapDataType, cuuint32_t,
                                     void*, const cuuint64_t*, const cuuint64_t*,
                                     const cuuint32_t*, const cuuint32_t*,
                                     CUtensorMapInterleave, CUtensorMapSwizzle,
                                     CUtensorMapL2promotion, CUtensorMapFloatOOBfill);

static void make_map(PFN_tmeTiled_v12 enc, CUtensorMap* m, void* addr,
                     unsigned long long cols, unsigned long long rows,
                     unsigned box_rows) {
    cuuint64_t dims[2]   = {cols, rows};
    cuuint64_t stride[1] = {cols * 2};
    cuuint32_t box[2]    = {64u, box_rows};
    cuuint32_t es[2]     = {1u, 1u};
    enc(m, CU_TENSOR_MAP_DATA_TYPE_FLOAT16, 2, addr, dims, stride, box, es,
        CU_TENSOR_MAP_INTERLEAVE_NONE, CU_TENSOR_MAP_SWIZZLE_128B,
        CU_TENSOR_MAP_L2_PROMOTION_L2_128B, CU_TENSOR_MAP_FLOAT_OOB_FILL_NONE);
}

// ---------------- launch ----------------
extern "C" void kernel_launch(void* const* d_in, const int* in_sizes, int n_in,
                              void* d_out, int out_size) {
    const float* x      = (const float*)d_in[0];
    const float* w_qkv  = (const float*)d_in[1];
    const float* b_qkv  = (const float*)d_in[2];
    const float* q_gamma= (const float*)d_in[3];
    const float* k_gamma= (const float*)d_in[4];
    const float* w_proj = (const float*)d_in[5];
    const float* b_proj = (const float*)d_in[6];
    float* out = (float*)d_out;

    cudaFuncSetAttribute(gemm_f16_kernel, cudaFuncAttributeMaxDynamicSharedMemorySize, GEMM_SMEM);
    cudaFuncSetAttribute(attn_f16_kernel, cudaFuncAttributeMaxDynamicSharedMemorySize, ATTN_SMEM);

    __half *xh, *wqh, *wph, *ah;
    cudaGetSymbolAddress((void**)&xh,  g_xh);
    cudaGetSymbolAddress((void**)&wqh, g_wqh);
    cudaGetSymbolAddress((void**)&wph, g_wph);
    cudaGetSymbolAddress((void**)&ah,  g_ah);

    // driver entry point for cuTensorMapEncodeTiled (no -lcuda needed)
    void* fptr = nullptr;
    cudaDriverEntryPointQueryResult qres;
    cudaGetDriverEntryPointByVersion("cuTensorMapEncodeTiled", &fptr, 12000,
                                     cudaEnableDefault, &qres);
    PFN_tmeTiled_v12 enc = (PFN_tmeTiled_v12)fptr;

    CUtensorMap mAq, mBq, mAp, mBp;
    make_map(enc, &mAq, xh,  HIDDEN, M_TOT,  256);   // QKV A
    make_map(enc, &mBq, wqh, HIDDEN, N_QKV,  128);   // QKV B
    make_map(enc, &mAp, ah,  HIDDEN, M_TOT,  256);   // proj A
    make_map(enc, &mBp, wph, HIDDEN, HIDDEN, 128);   // proj B

    {   // fp32 -> fp16 conversions
        int n8x = M_TOT*HIDDEN/8, n8q = N_QKV*HIDDEN/8, n8p = HIDDEN*HIDDEN/8;
        conv_h_kernel<<<(n8x+255)/256, 256>>>((const float4*)x, (uint4*)xh, n8x);
        conv_h_kernel<<<(n8q+255)/256, 256>>>((const float4*)w_qkv, (uint4*)wqh, n8q);
        conv_h_kernel<<<(n8p+255)/256, 256>>>((const float4*)w_proj, (uint4*)wph, n8p);
    }
    {   // QKV projection
        dim3 grid(N_QKV/128, M_TOT/256);   // (27, 64)
        gemm_f16_kernel<<<grid, 256, GEMM_SMEM>>>(mAq, mBq, b_qkv, nullptr, 0);
    }
    {   // fused RMSNorm (q + k in one launch)
        dim3 grid(BATCH*HEADS*SEQ/8, 2);
        rmsnorm_h_kernel<<<grid, 256>>>(q_gamma, k_gamma);
    }
    {   // attention
        dim3 grid(SEQ/128, HEADS, BATCH);  // (8,16,16)
        attn_f16_kernel<<<grid, 256, ATTN_SMEM>>>();
    }
    {   // output projection
        dim3 grid(HIDDEN/128, M_TOT/256);  // (9, 64)
        gemm_f16_kernel<<<grid, 256, GEMM_SMEM>>>(mAp, mBp, b_proj, out, 1);
    }
}

// round 11
// speedup vs baseline: 1.7498x; 1.0666x over previous
#include <cuda_runtime.h>
#include <cuda.h>
#include <cuda_fp16.h>
#include <math.h>

#define HIDDEN 1152
#define HEADS  16
#define HD     72
#define BATCH  16
#define SEQ    1024
#define M_TOT  (BATCH*SEQ)
#define N_QKV  (3*HIDDEN)
#define QSCALE 0.11785113f
#define RMS_EPS 1.1920928955078125e-07f

// ---------------- scratch ----------------
__device__ __align__(256) __half g_qh[(size_t)BATCH*HEADS*SEQ*HD];
__device__ __align__(256) __half g_kh[(size_t)BATCH*HEADS*SEQ*HD];
__device__ __align__(256) __half g_vh[(size_t)BATCH*HEADS*SEQ*HD];
__device__ __align__(256) __half g_ah[(size_t)M_TOT*HIDDEN];
__device__ __align__(256) __half g_xh[(size_t)M_TOT*HIDDEN];
__device__ __align__(256) __half g_wqh[(size_t)N_QKV*HIDDEN];
__device__ __align__(256) __half g_wph[(size_t)HIDDEN*HIDDEN];

// ---------------- helpers ----------------
__device__ __forceinline__ unsigned h2u(__half2 h) {
    unsigned u;
    asm("mov.b32 %0, %1;" : "=r"(u) : "r"(*(unsigned*)&h));
    return u;
}
__device__ __forceinline__ unsigned sptr(const void* p) {
    return (unsigned)__cvta_generic_to_shared(p);
}
__device__ __forceinline__ void ldsm4(unsigned r[4], const void* p) {
    asm volatile("ldmatrix.sync.aligned.m8n8.x4.shared.b16 {%0,%1,%2,%3},[%4];"
                 : "=r"(r[0]), "=r"(r[1]), "=r"(r[2]), "=r"(r[3]) : "r"(sptr(p)));
}
__device__ __forceinline__ void ldsm4t(unsigned r[4], const void* p) {
    asm volatile("ldmatrix.sync.aligned.m8n8.x4.trans.shared.b16 {%0,%1,%2,%3},[%4];"
                 : "=r"(r[0]), "=r"(r[1]), "=r"(r[2]), "=r"(r[3]) : "r"(sptr(p)));
}
__device__ __forceinline__ void ldsm2t(unsigned r[2], const void* p) {
    asm volatile("ldmatrix.sync.aligned.m8n8.x2.trans.shared.b16 {%0,%1},[%2];"
                 : "=r"(r[0]), "=r"(r[1]) : "r"(sptr(p)));
}
__device__ __forceinline__ void mma16816(float c[4], const unsigned a[4],
                                         unsigned b0, unsigned b1) {
    asm volatile(
        "mma.sync.aligned.m16n8k16.row.col.f32.f16.f16.f32 "
        "{%0,%1,%2,%3},{%4,%5,%6,%7},{%8,%9},{%0,%1,%2,%3};"
        : "+f"(c[0]), "+f"(c[1]), "+f"(c[2]), "+f"(c[3])
        : "r"(a[0]), "r"(a[1]), "r"(a[2]), "r"(a[3]), "r"(b0), "r"(b1));
}
__device__ __forceinline__ void cp16(void* smem, const void* g) {
    asm volatile("cp.async.ca.shared.global [%0], [%1], 16;" :: "r"(sptr(smem)), "l"(g));
}
__device__ __forceinline__ void cp_commit() { asm volatile("cp.async.commit_group;"); }
__device__ __forceinline__ void cp_wait0()  { asm volatile("cp.async.wait_group 0;"); }
__device__ __forceinline__ void cp_wait1()  { asm volatile("cp.async.wait_group 1;"); }

__device__ __forceinline__ void mbar_init(unsigned mbar, unsigned count) {
    asm volatile("mbarrier.init.shared.b64 [%0], %1;" :: "r"(mbar), "r"(count) : "memory");
}
__device__ __forceinline__ void mbar_expect_tx(unsigned mbar, unsigned bytes) {
    asm volatile("mbarrier.arrive.expect_tx.shared::cta.b64 _, [%0], %1;"
                 :: "r"(mbar), "r"(bytes) : "memory");
}
__device__ __forceinline__ void mbar_arrive(unsigned mbar) {
    asm volatile("mbarrier.arrive.shared::cta.b64 _, [%0];" :: "r"(mbar) : "memory");
}
__device__ __forceinline__ void mbar_wait(unsigned mbar, unsigned parity) {
    asm volatile(
        "{\n\t.reg .pred P;\n\t"
        "LW%=: mbarrier.try_wait.parity.acquire.cta.shared::cta.b64 P, [%0], %1, 0x989680;\n\t"
        "@P bra LD%=;\n\t"
        "bra LW%=;\n\t"
        "LD%=:\n\t}"
        :: "r"(mbar), "r"(parity) : "memory");
}
__device__ __forceinline__ void tma2d(unsigned smem, const CUtensorMap* m,
                                      int cx, int cy, unsigned mbar) {
    asm volatile(
        "cp.async.bulk.tensor.2d.shared::cta.global.tile.mbarrier::complete_tx::bytes "
        "[%0], [%1, {%2, %3}], [%4];"
        :: "r"(smem), "l"(m), "r"(cx), "r"(cy), "r"(mbar) : "memory");
}

// ---------------- fp32 -> fp16 conversion ----------------
__global__ __launch_bounds__(256) void conv_h_kernel(const float4* __restrict__ src,
                                                     uint4* __restrict__ dst, int n8) {
    int i = blockIdx.x * 256 + threadIdx.x;
    if (i < n8) {
        float4 f0 = src[2*i], f1 = src[2*i+1];
        uint4 o;
        o.x = h2u(__floats2half2_rn(f0.x, f0.y));
        o.y = h2u(__floats2half2_rn(f0.z, f0.w));
        o.z = h2u(__floats2half2_rn(f1.x, f1.y));
        o.w = h2u(__floats2half2_rn(f1.z, f1.w));
        dst[i] = o;
    }
}

// =======================================================================
// fp16 GEMM, warp-specialized: BM=256 BN=128 BK=64.
// 288 threads = 8 compute warps (4x2, 64x64 tiles) + 1 TMA producer warp.
// 4-slot mbarrier ring; NO per-stage __syncthreads — slot reuse guarded by
// consumer-arrive mbarriers (count 8).
// =======================================================================
#define GA_ST 16384   // halves per A slot (256 rows x 64)
#define GB_ST 8192    // halves per B slot (128 rows x 64)
#define STAGE_BYTES ((GA_ST+GB_ST)*2)          // 49152
#define NSLOT 4
#define GEMM_SMEM (NSLOT*STAGE_BYTES + 128)    // 196736

__global__ __launch_bounds__(288) void gemm_f16_kernel(
        const __grid_constant__ CUtensorMap mA,
        const __grid_constant__ CUtensorMap mB,
        const float* __restrict__ bias,
        float* __restrict__ out, int mode) {
    extern __shared__ __half hsm[];
    __half* As = hsm;                        // 4 x GA_ST
    __half* Bs = hsm + NSLOT*GA_ST;          // 4 x GB_ST
    const unsigned mb = sptr(hsm) + NSLOT*STAGE_BYTES;  // full[4]@0, cons[4]@32

    const int tid  = threadIdx.x;
    const int warp = tid >> 5;
    const int lane = tid & 31;

    const int m0 = blockIdx.y * 256;
    const int n0 = blockIdx.x * 128;
    const int NS = HIDDEN / 64;   // 18

    if (tid < 4)      mbar_init(mb + tid*8, 1);        // full: TMA tx
    else if (tid < 8) mbar_init(mb + tid*8, 8);        // cons: 8 compute warps
    __syncthreads();

    // ---------------- producer warp ----------------
    if (warp == 8) {
        if (lane == 0) {
            for (int c = 0; c < NS; ++c) {
                const int slot = c & 3;
                if (c >= NSLOT) mbar_wait(mb + 32 + slot*8, ((c >> 2) - 1) & 1);
                mbar_expect_tx(mb + slot*8, STAGE_BYTES);
                tma2d(sptr(As + slot*GA_ST), &mA, c*64, m0, mb + slot*8);
                tma2d(sptr(Bs + slot*GB_ST), &mB, c*64, n0, mb + slot*8);
            }
        }
        return;
    }

    // ---------------- compute warps (0..7) ----------------
    const int wr = warp >> 1;     // 0..3
    const int wc = warp & 1;      // 0..1
    const int g  = lane >> 2;
    const int t  = lane & 3;

    float acc[4][8][4];
#pragma unroll
    for (int mi = 0; mi < 4; ++mi)
#pragma unroll
        for (int ni = 0; ni < 8; ++ni)
#pragma unroll
            for (int r = 0; r < 4; ++r) acc[mi][ni][r] = 0.f;

    const int a_rin  = lane & 15;
    const int a_koff = lane >> 4;
    const int b_nin  = (lane & 7) + ((lane >> 4) << 3);
    const int b_koff = (lane >> 3) & 1;

    for (int s = 0; s < NS; ++s) {
        const int slot = s & 3;
        mbar_wait(mb + slot*8, (s >> 2) & 1);
        const __half* cA = As + slot * GA_ST;
        const __half* cB = Bs + slot * GB_ST;
#pragma unroll
        for (int ks = 0; ks < 4; ++ks) {
            unsigned a[4][4];
#pragma unroll
            for (int mi = 0; mi < 4; ++mi) {
                const int row = wr*64 + mi*16 + a_rin;
                const int pc  = (ks*2 + a_koff) ^ (row & 7);
                ldsm4(a[mi], cA + (row*8 + pc)*8);
            }
            unsigned bf[8][2];
#pragma unroll
            for (int p = 0; p < 4; ++p) {
                const int row = wc*64 + p*16 + b_nin;
                const int pc  = (ks*2 + b_koff) ^ (row & 7);
                unsigned q[4];
                ldsm4(q, cB + (row*8 + pc)*8);
                bf[2*p][0] = q[0]; bf[2*p][1] = q[1];
                bf[2*p+1][0] = q[2]; bf[2*p+1][1] = q[3];
            }
#pragma unroll
            for (int mi = 0; mi < 4; ++mi)
#pragma unroll
                for (int ni = 0; ni < 8; ++ni)
                    mma16816(acc[mi][ni], a[mi], bf[ni][0], bf[ni][1]);
        }
        if (lane == 0) mbar_arrive(mb + 32 + slot*8);
    }

    // ---------------- epilogue ----------------
    if (mode == 0) {
        const int which = n0 / HIDDEN;
        __half* dst = (which == 0) ? g_qh : (which == 1) ? g_kh : g_vh;
#pragma unroll
        for (int mi = 0; mi < 4; ++mi)
#pragma unroll
            for (int ni = 0; ni < 8; ++ni) {
                const int col = n0 + wc*64 + ni*8 + 2*t;
                const int rem = col - which * HIDDEN;
                const int h   = rem / HD;
                const int d   = rem - h * HD;
                const float b0 = bias[col], b1 = bias[col + 1];
#pragma unroll
                for (int half_ = 0; half_ < 2; ++half_) {
                    const int row = m0 + wr*64 + mi*16 + g + half_*8;
                    const int bi  = row >> 10, si = row & (SEQ - 1);
                    __half2 v = __floats2half2_rn(acc[mi][ni][2*half_] + b0,
                                                  acc[mi][ni][2*half_+1] + b1);
                    *(__half2*)&dst[(((size_t)(bi*HEADS + h))*SEQ + si)*HD + d] = v;
                }
            }
    } else {
#pragma unroll
        for (int mi = 0; mi < 4; ++mi)
#pragma unroll
            for (int ni = 0; ni < 8; ++ni) {
                const int col = n0 + wc*64 + ni*8 + 2*t;
                const float b0 = bias[col], b1 = bias[col + 1];
#pragma unroll
                for (int half_ = 0; half_ < 2; ++half_) {
                    const int row = m0 + wr*64 + mi*16 + g + half_*8;
                    float2 v = make_float2(acc[mi][ni][2*half_] + b0,
                                           acc[mi][ni][2*half_+1] + b1);
                    *(float2*)&out[(size_t)row * HIDDEN + col] = v;
                }
            }
    }
}

// ---------------- fused RMSNorm: blockIdx.y 0 -> q (scaled), 1 -> k ----------------
__global__ __launch_bounds__(256) void rmsnorm_h_kernel(const float* __restrict__ q_gamma,
                                                        const float* __restrict__ k_gamma) {
    __half* tp = blockIdx.y ? g_kh : g_qh;
    const float* gamma = blockIdx.y ? k_gamma : q_gamma;
    const float scale = blockIdx.y ? 1.0f : QSCALE;
    const int row  = blockIdx.x * 8 + (threadIdx.x >> 5);
    const int lane = threadIdx.x & 31;
    __half* p = tp + (size_t)row * HD;
    float v0 = __half2float(p[lane]);
    float v1 = __half2float(p[32 + lane]);
    float v2 = (lane < 8) ? __half2float(p[64 + lane]) : 0.f;
    float ss = v0*v0 + v1*v1 + v2*v2;
#pragma unroll
    for (int o = 16; o; o >>= 1) ss += __shfl_xor_sync(0xffffffffu, ss, o);
    const float rs = rsqrtf(ss * (1.0f/72.0f) + RMS_EPS) * scale;
    p[lane]      = __float2half(v0 * rs * gamma[lane]);
    p[32 + lane] = __float2half(v1 * rs * gamma[32 + lane]);
    if (lane < 8) p[64 + lane] = __float2half(v2 * rs * gamma[64 + lane]);
}

// =======================================================================
// fp16 flash attention (R8/R9): NO online max, 3-stage KV ring, one sync/iter.
// =======================================================================
#define AQ_H (128*80)
#define AKV1 (64*80)
#define ATTN_SMEM ((AQ_H + 6*AKV1)*2)    // 81920 bytes

__global__ __launch_bounds__(256, 2) void attn_f16_kernel() {
    extern __shared__ __half asm_[];
    __half* Qs = asm_;
    __half* Ks = Qs + AQ_H;
    __half* Vs = Ks + 3*AKV1;

    const int qt = blockIdx.x;
    const int h  = blockIdx.y;
    const int b  = blockIdx.z;
    const int tid  = threadIdx.x;
    const int warp = tid >> 5;
    const int lane = tid & 31;
    const int g    = lane >> 2;
    const int t    = lane & 3;

    const size_t head_base = ((size_t)(b*HEADS + h)) * SEQ * HD;
    const __half* gQ = g_qh + head_base + (size_t)qt * 128 * HD;
    const __half* gK = g_kh + head_base;
    const __half* gV = g_vh + head_base;

    for (int r = tid; r < 512; r += 256) {
        __half* base;
        int rr;
        if (r < 128)      { base = Qs; rr = r; }
        else if (r < 320) { base = Ks; rr = r - 128; }
        else              { base = Vs; rr = r - 320; }
        *(uint4*)&base[(rr*10 + 9)*8] = make_uint4(0,0,0,0);
    }

    auto load_kv = [&](int kt) {
        __half* Kb = Ks + (kt % 3) * AKV1;
        __half* Vb = Vs + (kt % 3) * AKV1;
        const size_t base = (size_t)kt * 64 * HD;
        for (int idx = tid; idx < 1152; idx += 256) {
            const int arr = idx >= 576;
            const int rem = idx - 576*arr;
            const int row = rem / 9, c = rem - row*9;
            const int pc = (c < 8) ? (c ^ (row & 7)) : 8;
            if (arr) cp16(Vb + (row*10 + pc)*8, gV + base + row*HD + c*8);
            else     cp16(Kb + (row*10 + pc)*8, gK + base + row*HD + c*8);
        }
    };

    for (int idx = tid; idx < 1152; idx += 256) {
        const int row = idx / 9, c = idx - row*9;
        const int pc = (c < 8) ? (c ^ (row & 7)) : 8;
        cp16(Qs + (row*10 + pc)*8, gQ + row*HD + c*8);
    }
    load_kv(0);
    cp_commit();
    load_kv(1);
    cp_commit();

    float o[9][4];
#pragma unroll
    for (int n = 0; n < 9; ++n)
#pragma unroll
        for (int r = 0; r < 4; ++r) o[n][r] = 0.f;
    float l0 = 0.f, l1 = 0.f;

    const int a_rin  = lane & 15;
    const int a_koff = lane >> 4;
    const int b_nin  = (lane & 7) + ((lane >> 4) << 3);
    const int b_koff = (lane >> 3) & 1;
    const int v_sin  = (lane & 7) + ((lane >> 3) & 1) * 8;
    const int v_doff = lane >> 4;

    const int KT = SEQ / 64;   // 16

    for (int kt = 0; kt < KT; ++kt) {
        if (kt == KT - 1) cp_wait0(); else cp_wait1();
        __syncthreads();
        if (kt + 2 < KT) { load_kv(kt + 2); cp_commit(); }

        const __half* Kb = Ks + (kt % 3) * AKV1;
        const __half* Vb = Vs + (kt % 3) * AKV1;

        float c[8][4];
#pragma unroll
        for (int n = 0; n < 8; ++n)
#pragma unroll
            for (int r = 0; r < 4; ++r) c[n][r] = 0.f;
#pragma unroll
        for (int ks = 0; ks < 5; ++ks) {
            unsigned aq[4];
            {
                const int row = warp*16 + a_rin;
                const int ch  = 2*ks + a_koff;
                const int pc  = (ch < 8) ? (ch ^ (row & 7)) : ch;
                ldsm4(aq, Qs + (row*10 + pc)*8);
            }
#pragma unroll
            for (int p = 0; p < 4; ++p) {
                const int row = p*16 + b_nin;
                const int ch  = 2*ks + b_koff;
                const int pc  = (ch < 8) ? (ch ^ (row & 7)) : ch;
                unsigned q[4];
                ldsm4(q, Kb + (row*10 + pc)*8);
                mma16816(c[2*p],   aq, q[0], q[1]);
                mma16816(c[2*p+1], aq, q[2], q[3]);
            }
        }

        float sum0 = 0.f, sum1 = 0.f;
#pragma unroll
        for (int n = 0; n < 8; ++n) {
            c[n][0] = __expf(c[n][0]);
            c[n][1] = __expf(c[n][1]);
            c[n][2] = __expf(c[n][2]);
            c[n][3] = __expf(c[n][3]);
            sum0 += c[n][0] + c[n][1];
            sum1 += c[n][2] + c[n][3];
        }
        sum0 += __shfl_xor_sync(0xffffffffu, sum0, 1);
        sum0 += __shfl_xor_sync(0xffffffffu, sum0, 2);
        sum1 += __shfl_xor_sync(0xffffffffu, sum1, 1);
        sum1 += __shfl_xor_sync(0xffffffffu, sum1, 2);
        l0 += sum0;
        l1 += sum1;

        unsigned pa[4][4];
#pragma unroll
        for (int k2 = 0; k2 < 4; ++k2) {
            pa[k2][0] = h2u(__floats2half2_rn(c[2*k2][0],   c[2*k2][1]));
            pa[k2][1] = h2u(__floats2half2_rn(c[2*k2][2],   c[2*k2][3]));
            pa[k2][2] = h2u(__floats2half2_rn(c[2*k2+1][0], c[2*k2+1][1]));
            pa[k2][3] = h2u(__floats2half2_rn(c[2*k2+1][2], c[2*k2+1][3]));
        }

#pragma unroll
        for (int k2 = 0; k2 < 4; ++k2) {
#pragma unroll
            for (int p2 = 0; p2 < 4; ++p2) {
                const int srow = k2*16 + v_sin;
                const int ch   = 2*p2 + v_doff;
                const int pc   = ch ^ (srow & 7);
                unsigned q[4];
                ldsm4t(q, Vb + (srow*10 + pc)*8);
                mma16816(o[2*p2],   pa[k2], q[0], q[1]);
                mma16816(o[2*p2+1], pa[k2], q[2], q[3]);
            }
            {
                const int srow = k2*16 + v_sin;
                unsigned q2[2];
                ldsm2t(q2, Vb + (srow*10 + 8)*8);
                mma16816(o[8], pa[k2], q2[0], q2[1]);
            }
        }
    }

    const float inv0 = 1.0f / l0, inv1 = 1.0f / l1;
    const int q0 = qt*128 + warp*16 + g;
    __half* base0 = g_ah + ((size_t)(b*SEQ + q0)     * HIDDEN) + h*HD;
    __half* base1 = g_ah + ((size_t)(b*SEQ + q0 + 8) * HIDDEN) + h*HD;
#pragma unroll
    for (int n = 0; n < 9; ++n) {
        const int d = n*8 + 2*t;
        *(__half2*)&base0[d] = __floats2half2_rn(o[n][0]*inv0, o[n][1]*inv0);
        *(__half2*)&base1[d] = __floats2half2_rn(o[n][2]*inv1, o[n][3]*inv1);
    }
}

// ---------------- host: tensor-map encode via driver entry point ----------------
typedef CUresult (*PFN_tmeTiled_v12)(CUtensorMap*, CUtensorMapDataType, cuuint32_t,
                                     void*, const cuuint64_t*, const cuuint64_t*,
                                     const cuuint32_t*, const cuuint32_t*,
                                     CUtensorMapInterleave, CUtensorMapSwizzle,
                                     CUtensorMapL2promotion, CUtensorMapFloatOOBfill);

static void make_map(PFN_tmeTiled_v12 enc, CUtensorMap* m, void* addr,
                     unsigned long long cols, unsigned long long rows,
                     unsigned box_rows) {
    cuuint64_t dims[2]   = {cols, rows};
    cuuint64_t stride[1] = {cols * 2};
    cuuint32_t box[2]    = {64u, box_rows};
    cuuint32_t es[2]     = {1u, 1u};
    enc(m, CU_TENSOR_MAP_DATA_TYPE_FLOAT16, 2, addr, dims, stride, box, es,
        CU_TENSOR_MAP_INTERLEAVE_NONE, CU_TENSOR_MAP_SWIZZLE_128B,
        CU_TENSOR_MAP_L2_PROMOTION_L2_128B, CU_TENSOR_MAP_FLOAT_OOB_FILL_NONE);
}

// ---------------- launch ----------------
extern "C" void kernel_launch(void* const* d_in, const int* in_sizes, int n_in,
                              void* d_out, int out_size) {
    const float* x      = (const float*)d_in[0];
    const float* w_qkv  = (const float*)d_in[1];
    const float* b_qkv  = (const float*)d_in[2];
    const float* q_gamma= (const float*)d_in[3];
    const float* k_gamma= (const float*)d_in[4];
    const float* w_proj = (const float*)d_in[5];
    const float* b_proj = (const float*)d_in[6];
    float* out = (float*)d_out;

    cudaFuncSetAttribute(gemm_f16_kernel, cudaFuncAttributeMaxDynamicSharedMemorySize, GEMM_SMEM);
    cudaFuncSetAttribute(attn_f16_kernel, cudaFuncAttributeMaxDynamicSharedMemorySize, ATTN_SMEM);

    __half *xh, *wqh, *wph, *ah;
    cudaGetSymbolAddress((void**)&xh,  g_xh);
    cudaGetSymbolAddress((void**)&wqh, g_wqh);
    cudaGetSymbolAddress((void**)&wph, g_wph);
    cudaGetSymbolAddress((void**)&ah,  g_ah);

    void* fptr = nullptr;
    cudaDriverEntryPointQueryResult qres;
    cudaGetDriverEntryPointByVersion("cuTensorMapEncodeTiled", &fptr, 12000,
                                     cudaEnableDefault, &qres);
    PFN_tmeTiled_v12 enc = (PFN_tmeTiled_v12)fptr;

    CUtensorMap mAq, mBq, mAp, mBp;
    make_map(enc, &mAq, xh,  HIDDEN, M_TOT,  256);   // QKV A
    make_map(enc, &mBq, wqh, HIDDEN, N_QKV,  128);   // QKV B
    make_map(enc, &mAp, ah,  HIDDEN, M_TOT,  256);   // proj A
    make_map(enc, &mBp, wph, HIDDEN, HIDDEN, 128);   // proj B

    {   // fp32 -> fp16 conversions
        int n8x = M_TOT*HIDDEN/8, n8q = N_QKV*HIDDEN/8, n8p = HIDDEN*HIDDEN/8;
        conv_h_kernel<<<(n8x+255)/256, 256>>>((const float4*)x, (uint4*)xh, n8x);
        conv_h_kernel<<<(n8q+255)/256, 256>>>((const float4*)w_qkv, (uint4*)wqh, n8q);
        conv_h_kernel<<<(n8p+255)/256, 256>>>((const float4*)w_proj, (uint4*)wph, n8p);
    }
    {   // QKV projection
        dim3 grid(N_QKV/128, M_TOT/256);   // (27, 64)
        gemm_f16_kernel<<<grid, 288, GEMM_SMEM>>>(mAq, mBq, b_qkv, nullptr, 0);
    }
    {   // fused RMSNorm (q + k in one launch)
        dim3 grid(BATCH*HEADS*SEQ/8, 2);
        rmsnorm_h_kernel<<<grid, 256>>>(q_gamma, k_gamma);
    }
    {   // attention
        dim3 grid(SEQ/128, HEADS, BATCH);  // (8,16,16)
        attn_f16_kernel<<<grid, 256, ATTN_SMEM>>>();
    }
    {   // output projection
        dim3 grid(HIDDEN/128, M_TOT/256);  // (9, 64)
        gemm_f16_kernel<<<grid, 288, GEMM_SMEM>>>(mAp, mBp, b_proj, out, 1);
    }
}

// round 12
// speedup vs baseline: 1.9311x; 1.1037x over previous
#include <cuda_runtime.h>
#include <cuda.h>
#include <cuda_fp16.h>
#include <math.h>

#define HIDDEN 1152
#define HEADS  16
#define HD     72
#define BATCH  16
#define SEQ    1024
#define M_TOT  (BATCH*SEQ)
#define N_QKV  (3*HIDDEN)
#define QSCALE 0.11785113f
#define RMS_EPS 1.1920928955078125e-07f

// ---------------- scratch ----------------
__device__ __align__(256) __half g_qh[(size_t)BATCH*HEADS*SEQ*HD];
__device__ __align__(256) __half g_kh[(size_t)BATCH*HEADS*SEQ*HD];
__device__ __align__(256) __half g_vh[(size_t)BATCH*HEADS*SEQ*HD];
__device__ __align__(256) __half g_ah[(size_t)M_TOT*HIDDEN];
__device__ __align__(256) __half g_xh[(size_t)M_TOT*HIDDEN];
__device__ __align__(256) __half g_wqh[(size_t)N_QKV*HIDDEN];
__device__ __align__(256) __half g_wph[(size_t)HIDDEN*HIDDEN];

// ---------------- helpers ----------------
__device__ __forceinline__ unsigned h2u(__half2 h) {
    unsigned u;
    asm("mov.b32 %0, %1;" : "=r"(u) : "r"(*(unsigned*)&h));
    return u;
}
__device__ __forceinline__ unsigned sptr(const void* p) {
    return (unsigned)__cvta_generic_to_shared(p);
}
__device__ __forceinline__ void ldsm4(unsigned r[4], const void* p) {
    asm volatile("ldmatrix.sync.aligned.m8n8.x4.shared.b16 {%0,%1,%2,%3},[%4];"
                 : "=r"(r[0]), "=r"(r[1]), "=r"(r[2]), "=r"(r[3]) : "r"(sptr(p)));
}
__device__ __forceinline__ void ldsm2(unsigned r[2], const void* p) {
    asm volatile("ldmatrix.sync.aligned.m8n8.x2.shared.b16 {%0,%1},[%2];"
                 : "=r"(r[0]), "=r"(r[1]) : "r"(sptr(p)));
}
__device__ __forceinline__ void ldsm4t(unsigned r[4], const void* p) {
    asm volatile("ldmatrix.sync.aligned.m8n8.x4.trans.shared.b16 {%0,%1,%2,%3},[%4];"
                 : "=r"(r[0]), "=r"(r[1]), "=r"(r[2]), "=r"(r[3]) : "r"(sptr(p)));
}
__device__ __forceinline__ void ldsm2t(unsigned r[2], const void* p) {
    asm volatile("ldmatrix.sync.aligned.m8n8.x2.trans.shared.b16 {%0,%1},[%2];"
                 : "=r"(r[0]), "=r"(r[1]) : "r"(sptr(p)));
}
__device__ __forceinline__ void mma16816(float c[4], const unsigned a[4],
                                         unsigned b0, unsigned b1) {
    asm volatile(
        "mma.sync.aligned.m16n8k16.row.col.f32.f16.f16.f32 "
        "{%0,%1,%2,%3},{%4,%5,%6,%7},{%8,%9},{%0,%1,%2,%3};"
        : "+f"(c[0]), "+f"(c[1]), "+f"(c[2]), "+f"(c[3])
        : "r"(a[0]), "r"(a[1]), "r"(a[2]), "r"(a[3]), "r"(b0), "r"(b1));
}
__device__ __forceinline__ void mma16808(float c[4], unsigned a0, unsigned a1, unsigned b0) {
    asm volatile(
        "mma.sync.aligned.m16n8k8.row.col.f32.f16.f16.f32 "
        "{%0,%1,%2,%3},{%4,%5},{%6},{%0,%1,%2,%3};"
        : "+f"(c[0]), "+f"(c[1]), "+f"(c[2]), "+f"(c[3])
        : "r"(a0), "r"(a1), "r"(b0));
}

__device__ __forceinline__ void mbar_init(unsigned mbar, unsigned count) {
    asm volatile("mbarrier.init.shared.b64 [%0], %1;" :: "r"(mbar), "r"(count) : "memory");
}
__device__ __forceinline__ void mbar_expect_tx(unsigned mbar, unsigned bytes) {
    asm volatile("mbarrier.arrive.expect_tx.shared::cta.b64 _, [%0], %1;"
                 :: "r"(mbar), "r"(bytes) : "memory");
}
__device__ __forceinline__ void mbar_arrive(unsigned mbar) {
    asm volatile("mbarrier.arrive.shared::cta.b64 _, [%0];" :: "r"(mbar) : "memory");
}
__device__ __forceinline__ void mbar_wait(unsigned mbar, unsigned parity) {
    asm volatile(
        "{\n\t.reg .pred P;\n\t"
        "LW%=: mbarrier.try_wait.parity.acquire.cta.shared::cta.b64 P, [%0], %1, 0x989680;\n\t"
        "@P bra LD%=;\n\t"
        "bra LW%=;\n\t"
        "LD%=:\n\t}"
        :: "r"(mbar), "r"(parity) : "memory");
}
__device__ __forceinline__ void tma2d(unsigned smem, const CUtensorMap* m,
                                      int cx, int cy, unsigned mbar) {
    asm volatile(
        "cp.async.bulk.tensor.2d.shared::cta.global.tile.mbarrier::complete_tx::bytes "
        "[%0], [%1, {%2, %3}], [%4];"
        :: "r"(smem), "l"(m), "r"(cx), "r"(cy), "r"(mbar) : "memory");
}

// ---------------- fp32 -> fp16 conversion ----------------
__global__ __launch_bounds__(256) void conv_h_kernel(const float4* __restrict__ src,
                                                     uint4* __restrict__ dst, int n8) {
    int i = blockIdx.x * 256 + threadIdx.x;
    if (i < n8) {
        float4 f0 = src[2*i], f1 = src[2*i+1];
        uint4 o;
        o.x = h2u(__floats2half2_rn(f0.x, f0.y));
        o.y = h2u(__floats2half2_rn(f0.z, f0.w));
        o.z = h2u(__floats2half2_rn(f1.x, f1.y));
        o.w = h2u(__floats2half2_rn(f1.z, f1.w));
        dst[i] = o;
    }
}

// =======================================================================
// fp16 GEMM (R11): warp-specialized, BM=256 BN=128 BK=64, 288 threads =
// 8 compute warps + 1 TMA producer, 4-slot mbarrier ring, no per-stage bar.
// =======================================================================
#define GA_ST 16384
#define GB_ST 8192
#define STAGE_BYTES ((GA_ST+GB_ST)*2)
#define NSLOT 4
#define GEMM_SMEM (NSLOT*STAGE_BYTES + 128)

__global__ __launch_bounds__(288) void gemm_f16_kernel(
        const __grid_constant__ CUtensorMap mA,
        const __grid_constant__ CUtensorMap mB,
        const float* __restrict__ bias,
        float* __restrict__ out, int mode) {
    extern __shared__ __half hsm[];
    __half* As = hsm;
    __half* Bs = hsm + NSLOT*GA_ST;
    const unsigned mb = sptr(hsm) + NSLOT*STAGE_BYTES;

    const int tid  = threadIdx.x;
    const int warp = tid >> 5;
    const int lane = tid & 31;

    const int m0 = blockIdx.y * 256;
    const int n0 = blockIdx.x * 128;
    const int NS = HIDDEN / 64;

    if (tid < 4)      mbar_init(mb + tid*8, 1);
    else if (tid < 8) mbar_init(mb + tid*8, 8);
    __syncthreads();

    if (warp == 8) {
        if (lane == 0) {
            for (int c = 0; c < NS; ++c) {
                const int slot = c & 3;
                if (c >= NSLOT) mbar_wait(mb + 32 + slot*8, ((c >> 2) - 1) & 1);
                mbar_expect_tx(mb + slot*8, STAGE_BYTES);
                tma2d(sptr(As + slot*GA_ST), &mA, c*64, m0, mb + slot*8);
                tma2d(sptr(Bs + slot*GB_ST), &mB, c*64, n0, mb + slot*8);
            }
        }
        return;
    }

    const int wr = warp >> 1;
    const int wc = warp & 1;
    const int g  = lane >> 2;
    const int t  = lane & 3;

    float acc[4][8][4];
#pragma unroll
    for (int mi = 0; mi < 4; ++mi)
#pragma unroll
        for (int ni = 0; ni < 8; ++ni)
#pragma unroll
            for (int r = 0; r < 4; ++r) acc[mi][ni][r] = 0.f;

    const int a_rin  = lane & 15;
    const int a_koff = lane >> 4;
    const int b_nin  = (lane & 7) + ((lane >> 4) << 3);
    const int b_koff = (lane >> 3) & 1;

    for (int s = 0; s < NS; ++s) {
        const int slot = s & 3;
        mbar_wait(mb + slot*8, (s >> 2) & 1);
        const __half* cA = As + slot * GA_ST;
        const __half* cB = Bs + slot * GB_ST;
#pragma unroll
        for (int ks = 0; ks < 4; ++ks) {
            unsigned a[4][4];
#pragma unroll
            for (int mi = 0; mi < 4; ++mi) {
                const int row = wr*64 + mi*16 + a_rin;
                const int pc  = (ks*2 + a_koff) ^ (row & 7);
                ldsm4(a[mi], cA + (row*8 + pc)*8);
            }
            unsigned bf[8][2];
#pragma unroll
            for (int p = 0; p < 4; ++p) {
                const int row = wc*64 + p*16 + b_nin;
                const int pc  = (ks*2 + b_koff) ^ (row & 7);
                unsigned q[4];
                ldsm4(q, cB + (row*8 + pc)*8);
                bf[2*p][0] = q[0]; bf[2*p][1] = q[1];
                bf[2*p+1][0] = q[2]; bf[2*p+1][1] = q[3];
            }
#pragma unroll
            for (int mi = 0; mi < 4; ++mi)
#pragma unroll
                for (int ni = 0; ni < 8; ++ni)
                    mma16816(acc[mi][ni], a[mi], bf[ni][0], bf[ni][1]);
        }
        if (lane == 0) mbar_arrive(mb + 32 + slot*8);
    }

    if (mode == 0) {
        const int which = n0 / HIDDEN;
        __half* dst = (which == 0) ? g_qh : (which == 1) ? g_kh : g_vh;
#pragma unroll
        for (int mi = 0; mi < 4; ++mi)
#pragma unroll
            for (int ni = 0; ni < 8; ++ni) {
                const int col = n0 + wc*64 + ni*8 + 2*t;
                const int rem = col - which * HIDDEN;
                const int h   = rem / HD;
                const int d   = rem - h * HD;
                const float b0 = bias[col], b1 = bias[col + 1];
#pragma unroll
                for (int half_ = 0; half_ < 2; ++half_) {
                    const int row = m0 + wr*64 + mi*16 + g + half_*8;
                    const int bi  = row >> 10, si = row & (SEQ - 1);
                    __half2 v = __floats2half2_rn(acc[mi][ni][2*half_] + b0,
                                                  acc[mi][ni][2*half_+1] + b1);
                    *(__half2*)&dst[(((size_t)(bi*HEADS + h))*SEQ + si)*HD + d] = v;
                }
            }
    } else {
#pragma unroll
        for (int mi = 0; mi < 4; ++mi)
#pragma unroll
            for (int ni = 0; ni < 8; ++ni) {
                const int col = n0 + wc*64 + ni*8 + 2*t;
                const float b0 = bias[col], b1 = bias[col + 1];
#pragma unroll
                for (int half_ = 0; half_ < 2; ++half_) {
                    const int row = m0 + wr*64 + mi*16 + g + half_*8;
                    float2 v = make_float2(acc[mi][ni][2*half_] + b0,
                                           acc[mi][ni][2*half_+1] + b1);
                    *(float2*)&out[(size_t)row * HIDDEN + col] = v;
                }
            }
    }
}

// ---------------- fused RMSNorm: blockIdx.y 0 -> q (scaled), 1 -> k ----------------
__global__ __launch_bounds__(256) void rmsnorm_h_kernel(const float* __restrict__ q_gamma,
                                                        const float* __restrict__ k_gamma) {
    __half* tp = blockIdx.y ? g_kh : g_qh;
    const float* gamma = blockIdx.y ? k_gamma : q_gamma;
    const float scale = blockIdx.y ? 1.0f : QSCALE;
    const int row  = blockIdx.x * 8 + (threadIdx.x >> 5);
    const int lane = threadIdx.x & 31;
    __half* p = tp + (size_t)row * HD;
    float v0 = __half2float(p[lane]);
    float v1 = __half2float(p[32 + lane]);
    float v2 = (lane < 8) ? __half2float(p[64 + lane]) : 0.f;
    float ss = v0*v0 + v1*v1 + v2*v2;
#pragma unroll
    for (int o = 16; o; o >>= 1) ss += __shfl_xor_sync(0xffffffffu, ss, o);
    const float rs = rsqrtf(ss * (1.0f/72.0f) + RMS_EPS) * scale;
    p[lane]      = __float2half(v0 * rs * gamma[lane]);
    p[32 + lane] = __float2half(v1 * rs * gamma[32 + lane]);
    if (lane < 8) p[64 + lane] = __float2half(v2 * rs * gamma[64 + lane]);
}

// =======================================================================
// fp16 flash attention, TMA-fed: plain stride-72 smem (conflict-free:
// 72 halves = 36 words == 4 mod 32), 3-slot K+V mbarrier ring, single
// issuing thread, one __syncthreads per iter. d=72 = 4x k16 + 1x k8.
// =======================================================================
#define AQ_HALVES (128*HD)               // 9216
#define AKV_HALVES (64*HD)               // 4608
#define ASLOT_HALVES (2*AKV_HALVES)      // 9216 (K+V)
#define ATTN_DATA_B ((AQ_HALVES + 3*ASLOT_HALVES)*2)   // 73728
#define ATTN_SMEM (ATTN_DATA_B + 64)

__global__ __launch_bounds__(256, 2) void attn_f16_kernel(
        const __grid_constant__ CUtensorMap mQ,
        const __grid_constant__ CUtensorMap mK,
        const __grid_constant__ CUtensorMap mV) {
    extern __shared__ __half asm_[];
    __half* Qs = asm_;                                  // 128 x 72
    const unsigned mb = sptr(asm_) + ATTN_DATA_B;       // full[3]@0, qfull@24

    const int qt = blockIdx.x;
    const int h  = blockIdx.y;
    const int b  = blockIdx.z;
    const int tid  = threadIdx.x;
    const int warp = tid >> 5;
    const int lane = tid & 31;
    const int g    = lane >> 2;
    const int t    = lane & 3;

    const int rowbase = (b*HEADS + h) * SEQ;   // global row into [B*H*S, 72]

    if (tid < 4) mbar_init(mb + tid*8, 1);
    __syncthreads();

    if (tid == 0) {
        mbar_expect_tx(mb + 24, AQ_HALVES*2);
        tma2d(sptr(Qs), &mQ, 0, rowbase + qt*128, mb + 24);
#pragma unroll
        for (int c = 0; c < 2; ++c) {
            __half* Kb = asm_ + AQ_HALVES + c*ASLOT_HALVES;
            mbar_expect_tx(mb + c*8, ASLOT_HALVES*2);
            tma2d(sptr(Kb),              &mK, 0, rowbase + c*64, mb + c*8);
            tma2d(sptr(Kb + AKV_HALVES), &mV, 0, rowbase + c*64, mb + c*8);
        }
    }

    float o[9][4];
#pragma unroll
    for (int n = 0; n < 9; ++n)
#pragma unroll
        for (int r = 0; r < 4; ++r) o[n][r] = 0.f;
    float l0 = 0.f, l1 = 0.f;

    const int a_rin  = lane & 15;
    const int a_koff = lane >> 4;
    const int b_nin  = (lane & 7) + ((lane >> 4) << 3);
    const int b_koff = (lane >> 3) & 1;
    const int v_sin  = (lane & 7) + ((lane >> 3) & 1) * 8;
    const int v_doff = lane >> 4;
    const int rin16  = lane & 15;

    mbar_wait(mb + 24, 0);   // Q resident

    const int KT = SEQ / 64;   // 16

    for (int kt = 0; kt < KT; ++kt) {
        const int slot = kt % 3;
        mbar_wait(mb + slot*8, (kt/3) & 1);
        __syncthreads();   // all warps finished reading tile kt-1 -> slot (kt+2)%3 free
        if (tid == 0 && kt + 2 < KT) {
            const int s2 = (kt + 2) % 3;
            __half* Kb2 = asm_ + AQ_HALVES + s2*ASLOT_HALVES;
            mbar_expect_tx(mb + s2*8, ASLOT_HALVES*2);
            tma2d(sptr(Kb2),              &mK, 0, rowbase + (kt+2)*64, mb + s2*8);
            tma2d(sptr(Kb2 + AKV_HALVES), &mV, 0, rowbase + (kt+2)*64, mb + s2*8);
        }
        const __half* Kb = asm_ + AQ_HALVES + slot*ASLOT_HALVES;
        const __half* Vb = Kb + AKV_HALVES;

        // ---- S = Q @ K^T : 4x k16 + 1x k8 over d=72 ----
        float c[8][4];
#pragma unroll
        for (int n = 0; n < 8; ++n)
#pragma unroll
            for (int r = 0; r < 4; ++r) c[n][r] = 0.f;
#pragma unroll
        for (int ks = 0; ks < 4; ++ks) {
            unsigned aq[4];
            ldsm4(aq, Qs + (warp*16 + a_rin)*HD + ks*16 + a_koff*8);
#pragma unroll
            for (int p = 0; p < 4; ++p) {
                unsigned q[4];
                ldsm4(q, Kb + (p*16 + b_nin)*HD + ks*16 + b_koff*8);
                mma16816(c[2*p],   aq, q[0], q[1]);
                mma16816(c[2*p+1], aq, q[2], q[3]);
            }
        }
        {   // k8 tail: d 64..71
            unsigned aq2[2];
            ldsm2(aq2, Qs + (warp*16 + rin16)*HD + 64);
#pragma unroll
            for (int p = 0; p < 4; ++p) {
                unsigned kb2[2];
                ldsm2(kb2, Kb + (p*16 + rin16)*HD + 64);
                mma16808(c[2*p],   aq2[0], aq2[1], kb2[0]);
                mma16808(c[2*p+1], aq2[0], aq2[1], kb2[1]);
            }
        }

        // ---- softmax, no max subtraction (|score| <= sqrt(72)) ----
        float sum0 = 0.f, sum1 = 0.f;
#pragma unroll
        for (int n = 0; n < 8; ++n) {
            c[n][0] = __expf(c[n][0]);
            c[n][1] = __expf(c[n][1]);
            c[n][2] = __expf(c[n][2]);
            c[n][3] = __expf(c[n][3]);
            sum0 += c[n][0] + c[n][1];
            sum1 += c[n][2] + c[n][3];
        }
        sum0 += __shfl_xor_sync(0xffffffffu, sum0, 1);
        sum0 += __shfl_xor_sync(0xffffffffu, sum0, 2);
        sum1 += __shfl_xor_sync(0xffffffffu, sum1, 1);
        sum1 += __shfl_xor_sync(0xffffffffu, sum1, 2);
        l0 += sum0;
        l1 += sum1;

        unsigned pa[4][4];
#pragma unroll
        for (int k2 = 0; k2 < 4; ++k2) {
            pa[k2][0] = h2u(__floats2half2_rn(c[2*k2][0],   c[2*k2][1]));
            pa[k2][1] = h2u(__floats2half2_rn(c[2*k2][2],   c[2*k2][3]));
            pa[k2][2] = h2u(__floats2half2_rn(c[2*k2+1][0], c[2*k2+1][1]));
            pa[k2][3] = h2u(__floats2half2_rn(c[2*k2+1][2], c[2*k2+1][3]));
        }

        // ---- O += P @ V (V^T via ldmatrix.trans, stride 72) ----
#pragma unroll
        for (int k2 = 0; k2 < 4; ++k2) {
            const int srow = k2*16 + v_sin;
#pragma unroll
            for (int p2 = 0; p2 < 4; ++p2) {
                unsigned q[4];
                ldsm4t(q, Vb + srow*HD + (2*p2 + v_doff)*8);
                mma16816(o[2*p2],   pa[k2], q[0], q[1]);
                mma16816(o[2*p2+1], pa[k2], q[2], q[3]);
            }
            {
                unsigned q2[2];
                ldsm2t(q2, Vb + (k2*16 + v_sin)*HD + 64);
                mma16816(o[8], pa[k2], q2[0], q2[1]);
            }
        }
    }

    // ---- epilogue ----
    const float inv0 = 1.0f / l0, inv1 = 1.0f / l1;
    const int q0 = qt*128 + warp*16 + g;
    __half* base0 = g_ah + ((size_t)(b*SEQ + q0)     * HIDDEN) + h*HD;
    __half* base1 = g_ah + ((size_t)(b*SEQ + q0 + 8) * HIDDEN) + h*HD;
#pragma unroll
    for (int n = 0; n < 9; ++n) {
        const int d = n*8 + 2*t;
        *(__half2*)&base0[d] = __floats2half2_rn(o[n][0]*inv0, o[n][1]*inv0);
        *(__half2*)&base1[d] = __floats2half2_rn(o[n][2]*inv1, o[n][3]*inv1);
    }
}

// ---------------- host: tensor-map encode via driver entry point ----------------
typedef CUresult (*PFN_tmeTiled_v12)(CUtensorMap*, CUtensorMapDataType, cuuint32_t,
                                     void*, const cuuint64_t*, const cuuint64_t*,
                                     const cuuint32_t*, const cuuint32_t*,
                                     CUtensorMapInterleave, CUtensorMapSwizzle,
                                     CUtensorMapL2promotion, CUtensorMapFloatOOBfill);

static void make_map(PFN_tmeTiled_v12 enc, CUtensorMap* m, void* addr,
                     unsigned long long cols, unsigned long long rows,
                     unsigned box_rows) {
    cuuint64_t dims[2]   = {cols, rows};
    cuuint64_t stride[1] = {cols * 2};
    cuuint32_t box[2]    = {64u, box_rows};
    cuuint32_t es[2]     = {1u, 1u};
    enc(m, CU_TENSOR_MAP_DATA_TYPE_FLOAT16, 2, addr, dims, stride, box, es,
        CU_TENSOR_MAP_INTERLEAVE_NONE, CU_TENSOR_MAP_SWIZZLE_128B,
        CU_TENSOR_MAP_L2_PROMOTION_L2_128B, CU_TENSOR_MAP_FLOAT_OOB_FILL_NONE);
}

static void make_map_attn(PFN_tmeTiled_v12 enc, CUtensorMap* m, void* addr,
                          unsigned box_rows) {
    cuuint64_t dims[2]   = {HD, (cuuint64_t)BATCH*HEADS*SEQ};
    cuuint64_t stride[1] = {HD * 2};
    cuuint32_t box[2]    = {HD, box_rows};
    cuuint32_t es[2]     = {1u, 1u};
    enc(m, CU_TENSOR_MAP_DATA_TYPE_FLOAT16, 2, addr, dims, stride, box, es,
        CU_TENSOR_MAP_INTERLEAVE_NONE, CU_TENSOR_MAP_SWIZZLE_NONE,
        CU_TENSOR_MAP_L2_PROMOTION_L2_128B, CU_TENSOR_MAP_FLOAT_OOB_FILL_NONE);
}

// ---------------- launch ----------------
extern "C" void kernel_launch(void* const* d_in, const int* in_sizes, int n_in,
                              void* d_out, int out_size) {
    const float* x      = (const float*)d_in[0];
    const float* w_qkv  = (const float*)d_in[1];
    const float* b_qkv  = (const float*)d_in[2];
    const float* q_gamma= (const float*)d_in[3];
    const float* k_gamma= (const float*)d_in[4];
    const float* w_proj = (const float*)d_in[5];
    const float* b_proj = (const float*)d_in[6];
    float* out = (float*)d_out;

    cudaFuncSetAttribute(gemm_f16_kernel, cudaFuncAttributeMaxDynamicSharedMemorySize, GEMM_SMEM);
    cudaFuncSetAttribute(attn_f16_kernel, cudaFuncAttributeMaxDynamicSharedMemorySize, ATTN_SMEM);

    __half *xh, *wqh, *wph, *ah, *qh, *kh, *vh;
    cudaGetSymbolAddress((void**)&xh,  g_xh);
    cudaGetSymbolAddress((void**)&wqh, g_wqh);
    cudaGetSymbolAddress((void**)&wph, g_wph);
    cudaGetSymbolAddress((void**)&ah,  g_ah);
    cudaGetSymbolAddress((void**)&qh,  g_qh);
    cudaGetSymbolAddress((void**)&kh,  g_kh);
    cudaGetSymbolAddress((void**)&vh,  g_vh);

    void* fptr = nullptr;
    cudaDriverEntryPointQueryResult qres;
    cudaGetDriverEntryPointByVersion("cuTensorMapEncodeTiled", &fptr, 12000,
                                     cudaEnableDefault, &qres);
    PFN_tmeTiled_v12 enc = (PFN_tmeTiled_v12)fptr;

    CUtensorMap mAq, mBq, mAp, mBp, mQ, mK, mV;
    make_map(enc, &mAq, xh,  HIDDEN, M_TOT,  256);   // QKV A
    make_map(enc, &mBq, wqh, HIDDEN, N_QKV,  128);   // QKV B
    make_map(enc, &mAp, ah,  HIDDEN, M_TOT,  256);   // proj A
    make_map(enc, &mBp, wph, HIDDEN, HIDDEN, 128);   // proj B
    make_map_attn(enc, &mQ, qh, 128);
    make_map_attn(enc, &mK, kh, 64);
    make_map_attn(enc, &mV, vh, 64);

    {   // fp32 -> fp16 conversions
        int n8x = M_TOT*HIDDEN/8, n8q = N_QKV*HIDDEN/8, n8p = HIDDEN*HIDDEN/8;
        conv_h_kernel<<<(n8x+255)/256, 256>>>((const float4*)x, (uint4*)xh, n8x);
        conv_h_kernel<<<(n8q+255)/256, 256>>>((const float4*)w_qkv, (uint4*)wqh, n8q);
        conv_h_kernel<<<(n8p+255)/256, 256>>>((const float4*)w_proj, (uint4*)wph, n8p);
    }
    {   // QKV projection
        dim3 grid(N_QKV/128, M_TOT/256);   // (27, 64)
        gemm_f16_kernel<<<grid, 288, GEMM_SMEM>>>(mAq, mBq, b_qkv, nullptr, 0);
    }
    {   // fused RMSNorm (q + k in one launch)
        dim3 grid(BATCH*HEADS*SEQ/8, 2);
        rmsnorm_h_kernel<<<grid, 256>>>(q_gamma, k_gamma);
    }
    {   // attention (TMA-fed)
        dim3 grid(SEQ/128, HEADS, BATCH);  // (8,16,16)
        attn_f16_kernel<<<grid, 256, ATTN_SMEM>>>(mQ, mK, mV);
    }
    {   // output projection
        dim3 grid(HIDDEN/128, M_TOT/256);  // (9, 64)
        gemm_f16_kernel<<<grid, 288, GEMM_SMEM>>>(mAp, mBp, b_proj, out, 1);
    }
}

// round 13
// speedup vs baseline: 2.0054x; 1.0385x over previous
#include <cuda_runtime.h>
#include <cuda.h>
#include <cuda_fp16.h>
#include <math.h>

#define HIDDEN 1152
#define HEADS  16
#define HD     72
#define BATCH  16
#define SEQ    1024
#define M_TOT  (BATCH*SEQ)
#define N_QKV  (3*HIDDEN)
#define QSCALE 0.11785113f
#define RMS_EPS 1.1920928955078125e-07f

// ---------------- scratch ----------------
__device__ __align__(256) __half g_qh[(size_t)BATCH*HEADS*SEQ*HD];
__device__ __align__(256) __half g_kh[(size_t)BATCH*HEADS*SEQ*HD];
__device__ __align__(256) __half g_vh[(size_t)BATCH*HEADS*SEQ*HD];
__device__ __align__(256) __half g_ah[(size_t)M_TOT*HIDDEN];
__device__ __align__(256) __half g_xh[(size_t)M_TOT*HIDDEN];
__device__ __align__(256) __half g_wqh[(size_t)N_QKV*HIDDEN];
__device__ __align__(256) __half g_wph[(size_t)HIDDEN*HIDDEN];

// ---------------- helpers ----------------
__device__ __forceinline__ unsigned h2u(__half2 h) {
    unsigned u;
    asm("mov.b32 %0, %1;" : "=r"(u) : "r"(*(unsigned*)&h));
    return u;
}
__device__ __forceinline__ unsigned sptr(const void* p) {
    return (unsigned)__cvta_generic_to_shared(p);
}
__device__ __forceinline__ void ldsm4(unsigned r[4], const void* p) {
    asm volatile("ldmatrix.sync.aligned.m8n8.x4.shared.b16 {%0,%1,%2,%3},[%4];"
                 : "=r"(r[0]), "=r"(r[1]), "=r"(r[2]), "=r"(r[3]) : "r"(sptr(p)));
}
__device__ __forceinline__ void ldsm2(unsigned r[2], const void* p) {
    asm volatile("ldmatrix.sync.aligned.m8n8.x2.shared.b16 {%0,%1},[%2];"
                 : "=r"(r[0]), "=r"(r[1]) : "r"(sptr(p)));
}
__device__ __forceinline__ void ldsm4t(unsigned r[4], const void* p) {
    asm volatile("ldmatrix.sync.aligned.m8n8.x4.trans.shared.b16 {%0,%1,%2,%3},[%4];"
                 : "=r"(r[0]), "=r"(r[1]), "=r"(r[2]), "=r"(r[3]) : "r"(sptr(p)));
}
__device__ __forceinline__ void ldsm2t(unsigned r[2], const void* p) {
    asm volatile("ldmatrix.sync.aligned.m8n8.x2.trans.shared.b16 {%0,%1},[%2];"
                 : "=r"(r[0]), "=r"(r[1]) : "r"(sptr(p)));
}
__device__ __forceinline__ void mma16816(float c[4], const unsigned a[4],
                                         unsigned b0, unsigned b1) {
    asm volatile(
        "mma.sync.aligned.m16n8k16.row.col.f32.f16.f16.f32 "
        "{%0,%1,%2,%3},{%4,%5,%6,%7},{%8,%9},{%0,%1,%2,%3};"
        : "+f"(c[0]), "+f"(c[1]), "+f"(c[2]), "+f"(c[3])
        : "r"(a[0]), "r"(a[1]), "r"(a[2]), "r"(a[3]), "r"(b0), "r"(b1));
}
__device__ __forceinline__ void mma16808(float c[4], unsigned a0, unsigned a1, unsigned b0) {
    asm volatile(
        "mma.sync.aligned.m16n8k8.row.col.f32.f16.f16.f32 "
        "{%0,%1,%2,%3},{%4,%5},{%6},{%0,%1,%2,%3};"
        : "+f"(c[0]), "+f"(c[1]), "+f"(c[2]), "+f"(c[3])
        : "r"(a0), "r"(a1), "r"(b0));
}

__device__ __forceinline__ void mbar_init(unsigned mbar, unsigned count) {
    asm volatile("mbarrier.init.shared.b64 [%0], %1;" :: "r"(mbar), "r"(count) : "memory");
}
__device__ __forceinline__ void mbar_expect_tx(unsigned mbar, unsigned bytes) {
    asm volatile("mbarrier.arrive.expect_tx.shared::cta.b64 _, [%0], %1;"
                 :: "r"(mbar), "r"(bytes) : "memory");
}
__device__ __forceinline__ void mbar_arrive(unsigned mbar) {
    asm volatile("mbarrier.arrive.shared::cta.b64 _, [%0];" :: "r"(mbar) : "memory");
}
__device__ __forceinline__ void mbar_wait(unsigned mbar, unsigned parity) {
    asm volatile(
        "{\n\t.reg .pred P;\n\t"
        "LW%=: mbarrier.try_wait.parity.acquire.cta.shared::cta.b64 P, [%0], %1, 0x989680;\n\t"
        "@P bra LD%=;\n\t"
        "bra LW%=;\n\t"
        "LD%=:\n\t}"
        :: "r"(mbar), "r"(parity) : "memory");
}
__device__ __forceinline__ void tma2d(unsigned smem, const CUtensorMap* m,
                                      int cx, int cy, unsigned mbar) {
    asm volatile(
        "cp.async.bulk.tensor.2d.shared::cta.global.tile.mbarrier::complete_tx::bytes "
        "[%0], [%1, {%2, %3}], [%4];"
        :: "r"(smem), "l"(m), "r"(cx), "r"(cy), "r"(mbar) : "memory");
}

// ---------------- merged fp32 -> fp16 conversion (one launch) ----------------
#define N8X (M_TOT*HIDDEN/8)
#define N8Q (N_QKV*HIDDEN/8)
#define N8P (HIDDEN*HIDDEN/8)
__global__ __launch_bounds__(256) void conv_all_kernel(const float4* __restrict__ x,
                                                       const float4* __restrict__ wq,
                                                       const float4* __restrict__ wp,
                                                       uint4* __restrict__ xh,
                                                       uint4* __restrict__ wqh,
                                                       uint4* __restrict__ wph) {
    int i = blockIdx.x * 256 + threadIdx.x;
    const float4* src;
    uint4* dst;
    int j;
    if (i < N8X)            { src = x;  dst = xh;  j = i; }
    else if (i < N8X + N8Q) { src = wq; dst = wqh; j = i - N8X; }
    else if (i < N8X + N8Q + N8P) { src = wp; dst = wph; j = i - N8X - N8Q; }
    else return;
    float4 f0 = src[2*j], f1 = src[2*j+1];
    uint4 o;
    o.x = h2u(__floats2half2_rn(f0.x, f0.y));
    o.y = h2u(__floats2half2_rn(f0.z, f0.w));
    o.z = h2u(__floats2half2_rn(f1.x, f1.y));
    o.w = h2u(__floats2half2_rn(f1.z, f1.w));
    dst[j] = o;
}

// =======================================================================
// fp16 GEMM (R11 + early slot release): warp-specialized, BM=256 BN=128
// BK=64, 288 threads = 8 compute + 1 producer warp, 4-slot mbarrier ring.
// cons-arrive fires after the stage's LAST ldmatrix (not after the MMAs).
// =======================================================================
#define GA_ST 16384
#define GB_ST 8192
#define STAGE_BYTES ((GA_ST+GB_ST)*2)
#define NSLOT 4
#define GEMM_SMEM (NSLOT*STAGE_BYTES + 128)

__global__ __launch_bounds__(288) void gemm_f16_kernel(
        const __grid_constant__ CUtensorMap mA,
        const __grid_constant__ CUtensorMap mB,
        const float* __restrict__ bias,
        float* __restrict__ out, int mode) {
    extern __shared__ __half hsm[];
    __half* As = hsm;
    __half* Bs = hsm + NSLOT*GA_ST;
    const unsigned mb = sptr(hsm) + NSLOT*STAGE_BYTES;

    const int tid  = threadIdx.x;
    const int warp = tid >> 5;
    const int lane = tid & 31;

    const int m0 = blockIdx.y * 256;
    const int n0 = blockIdx.x * 128;
    const int NS = HIDDEN / 64;

    if (tid < 4)      mbar_init(mb + tid*8, 1);
    else if (tid < 8) mbar_init(mb + tid*8, 8);
    __syncthreads();

    if (warp == 8) {
        if (lane == 0) {
            for (int c = 0; c < NS; ++c) {
                const int slot = c & 3;
                if (c >= NSLOT) mbar_wait(mb + 32 + slot*8, ((c >> 2) - 1) & 1);
                mbar_expect_tx(mb + slot*8, STAGE_BYTES);
                tma2d(sptr(As + slot*GA_ST), &mA, c*64, m0, mb + slot*8);
                tma2d(sptr(Bs + slot*GB_ST), &mB, c*64, n0, mb + slot*8);
            }
        }
        return;
    }

    const int wr = warp >> 1;
    const int wc = warp & 1;
    const int g  = lane >> 2;
    const int t  = lane & 3;

    float acc[4][8][4];
#pragma unroll
    for (int mi = 0; mi < 4; ++mi)
#pragma unroll
        for (int ni = 0; ni < 8; ++ni)
#pragma unroll
            for (int r = 0; r < 4; ++r) acc[mi][ni][r] = 0.f;

    const int a_rin  = lane & 15;
    const int a_koff = lane >> 4;
    const int b_nin  = (lane & 7) + ((lane >> 4) << 3);
    const int b_koff = (lane >> 3) & 1;

    for (int s = 0; s < NS; ++s) {
        const int slot = s & 3;
        mbar_wait(mb + slot*8, (s >> 2) & 1);
        const __half* cA = As + slot * GA_ST;
        const __half* cB = Bs + slot * GB_ST;
#pragma unroll
        for (int ks = 0; ks < 4; ++ks) {
            unsigned a[4][4];
#pragma unroll
            for (int mi = 0; mi < 4; ++mi) {
                const int row = wr*64 + mi*16 + a_rin;
                const int pc  = (ks*2 + a_koff) ^ (row & 7);
                ldsm4(a[mi], cA + (row*8 + pc)*8);
            }
            unsigned bf[8][2];
#pragma unroll
            for (int p = 0; p < 4; ++p) {
                const int row = wc*64 + p*16 + b_nin;
                const int pc  = (ks*2 + b_koff) ^ (row & 7);
                unsigned q[4];
                ldsm4(q, cB + (row*8 + pc)*8);
                bf[2*p][0] = q[0]; bf[2*p][1] = q[1];
                bf[2*p+1][0] = q[2]; bf[2*p+1][1] = q[3];
            }
            // slot's smem fully consumed after this stage's final ldmatrix
            if (ks == 3 && lane == 0) mbar_arrive(mb + 32 + slot*8);
#pragma unroll
            for (int mi = 0; mi < 4; ++mi)
#pragma unroll
                for (int ni = 0; ni < 8; ++ni)
                    mma16816(acc[mi][ni], a[mi], bf[ni][0], bf[ni][1]);
        }
    }

    if (mode == 0) {
        const int which = n0 / HIDDEN;
        __half* dst = (which == 0) ? g_qh : (which == 1) ? g_kh : g_vh;
#pragma unroll
        for (int mi = 0; mi < 4; ++mi)
#pragma unroll
            for (int ni = 0; ni < 8; ++ni) {
                const int col = n0 + wc*64 + ni*8 + 2*t;
                const int rem = col - which * HIDDEN;
                const int h   = rem / HD;
                const int d   = rem - h * HD;
                const float b0 = bias[col], b1 = bias[col + 1];
#pragma unroll
                for (int half_ = 0; half_ < 2; ++half_) {
                    const int row = m0 + wr*64 + mi*16 + g + half_*8;
                    const int bi  = row >> 10, si = row & (SEQ - 1);
                    __half2 v = __floats2half2_rn(acc[mi][ni][2*half_] + b0,
                                                  acc[mi][ni][2*half_+1] + b1);
                    *(__half2*)&dst[(((size_t)(bi*HEADS + h))*SEQ + si)*HD + d] = v;
                }
            }
    } else {
#pragma unroll
        for (int mi = 0; mi < 4; ++mi)
#pragma unroll
            for (int ni = 0; ni < 8; ++ni) {
                const int col = n0 + wc*64 + ni*8 + 2*t;
                const float b0 = bias[col], b1 = bias[col + 1];
#pragma unroll
                for (int half_ = 0; half_ < 2; ++half_) {
                    const int row = m0 + wr*64 + mi*16 + g + half_*8;
                    float2 v = make_float2(acc[mi][ni][2*half_] + b0,
                                           acc[mi][ni][2*half_+1] + b1);
                    *(float2*)&out[(size_t)row * HIDDEN + col] = v;
                }
            }
    }
}

// ---------------- fused RMSNorm: blockIdx.y 0 -> q (scaled), 1 -> k ----------------
__global__ __launch_bounds__(256) void rmsnorm_h_kernel(const float* __restrict__ q_gamma,
                                                        const float* __restrict__ k_gamma) {
    __half* tp = blockIdx.y ? g_kh : g_qh;
    const float* gamma = blockIdx.y ? k_gamma : q_gamma;
    const float scale = blockIdx.y ? 1.0f : QSCALE;
    const int row  = blockIdx.x * 8 + (threadIdx.x >> 5);
    const int lane = threadIdx.x & 31;
    __half* p = tp + (size_t)row * HD;
    float v0 = __half2float(p[lane]);
    float v1 = __half2float(p[32 + lane]);
    float v2 = (lane < 8) ? __half2float(p[64 + lane]) : 0.f;
    float ss = v0*v0 + v1*v1 + v2*v2;
#pragma unroll
    for (int o = 16; o; o >>= 1) ss += __shfl_xor_sync(0xffffffffu, ss, o);
    const float rs = rsqrtf(ss * (1.0f/72.0f) + RMS_EPS) * scale;
    p[lane]      = __float2half(v0 * rs * gamma[lane]);
    p[32 + lane] = __float2half(v1 * rs * gamma[32 + lane]);
    if (lane < 8) p[64 + lane] = __float2half(v2 * rs * gamma[64 + lane]);
}

// =======================================================================
// fp16 flash attention, TMA-fed, DECOUPLED: no per-iter __syncthreads.
// full[3] (tx) + cons[3] (count 8) mbarriers; tid0 produces, all warps
// arrive on cons after their smem reads. Plain stride-72 smem.
// =======================================================================
#define AQ_HALVES (128*HD)
#define AKV_HALVES (64*HD)
#define ASLOT_HALVES (2*AKV_HALVES)
#define ATTN_DATA_B ((AQ_HALVES + 3*ASLOT_HALVES)*2)   // 73728
#define ATTN_SMEM (ATTN_DATA_B + 64)

__global__ __launch_bounds__(256, 2) void attn_f16_kernel(
        const __grid_constant__ CUtensorMap mQ,
        const __grid_constant__ CUtensorMap mK,
        const __grid_constant__ CUtensorMap mV) {
    extern __shared__ __half asm_[];
    __half* Qs = asm_;                                  // 128 x 72
    const unsigned mb = sptr(asm_) + ATTN_DATA_B;       // full[3]@0, qfull@24, cons[3]@32

    const int qt = blockIdx.x;
    const int h  = blockIdx.y;
    const int b  = blockIdx.z;
    const int tid  = threadIdx.x;
    const int warp = tid >> 5;
    const int lane = tid & 31;
    const int g    = lane >> 2;
    const int t    = lane & 3;

    const int rowbase = (b*HEADS + h) * SEQ;

    if (tid < 4)      mbar_init(mb + tid*8, 1);
    else if (tid < 7) mbar_init(mb + tid*8, 8);
    __syncthreads();

    if (tid == 0) {
        mbar_expect_tx(mb + 24, AQ_HALVES*2);
        tma2d(sptr(Qs), &mQ, 0, rowbase + qt*128, mb + 24);
#pragma unroll
        for (int c = 0; c < 2; ++c) {
            __half* Kb = asm_ + AQ_HALVES + c*ASLOT_HALVES;
            mbar_expect_tx(mb + c*8, ASLOT_HALVES*2);
            tma2d(sptr(Kb),              &mK, 0, rowbase + c*64, mb + c*8);
            tma2d(sptr(Kb + AKV_HALVES), &mV, 0, rowbase + c*64, mb + c*8);
        }
    }

    float o[9][4];
#pragma unroll
    for (int n = 0; n < 9; ++n)
#pragma unroll
        for (int r = 0; r < 4; ++r) o[n][r] = 0.f;
    float l0 = 0.f, l1 = 0.f;

    const int a_rin  = lane & 15;
    const int a_koff = lane >> 4;
    const int b_nin  = (lane & 7) + ((lane >> 4) << 3);
    const int b_koff = (lane >> 3) & 1;
    const int v_sin  = (lane & 7) + ((lane >> 3) & 1) * 8;
    const int v_doff = lane >> 4;
    const int rin16  = lane & 15;

    mbar_wait(mb + 24, 0);   // Q resident

    const int KT = SEQ / 64;   // 16

    for (int kt = 0; kt < KT; ++kt) {
        const int slot = kt % 3;
        // producer: refill slot (kt+2)%3 once its previous tile is consumed
        if (tid == 0 && kt + 2 < KT) {
            const int c2 = kt + 2;
            const int s2 = c2 % 3;
            if (c2 >= 3) mbar_wait(mb + 32 + s2*8, ((c2/3) - 1) & 1);
            __half* Kb2 = asm_ + AQ_HALVES + s2*ASLOT_HALVES;
            mbar_expect_tx(mb + s2*8, ASLOT_HALVES*2);
            tma2d(sptr(Kb2),              &mK, 0, rowbase + c2*64, mb + s2*8);
            tma2d(sptr(Kb2 + AKV_HALVES), &mV, 0, rowbase + c2*64, mb + s2*8);
        }
        mbar_wait(mb + slot*8, (kt/3) & 1);
        const __half* Kb = asm_ + AQ_HALVES + slot*ASLOT_HALVES;
        const __half* Vb = Kb + AKV_HALVES;

        // ---- S = Q @ K^T : 4x k16 + 1x k8 over d=72 ----
        float c[8][4];
#pragma unroll
        for (int n = 0; n < 8; ++n)
#pragma unroll
            for (int r = 0; r < 4; ++r) c[n][r] = 0.f;
#pragma unroll
        for (int ks = 0; ks < 4; ++ks) {
            unsigned aq[4];
            ldsm4(aq, Qs + (warp*16 + a_rin)*HD + ks*16 + a_koff*8);
#pragma unroll
            for (int p = 0; p < 4; ++p) {
                unsigned q[4];
                ldsm4(q, Kb + (p*16 + b_nin)*HD + ks*16 + b_koff*8);
                mma16816(c[2*p],   aq, q[0], q[1]);
                mma16816(c[2*p+1], aq, q[2], q[3]);
            }
        }
        {   // k8 tail
            unsigned aq2[2];
            ldsm2(aq2, Qs + (warp*16 + rin16)*HD + 64);
#pragma unroll
            for (int p = 0; p < 4; ++p) {
                unsigned kb2[2];
                ldsm2(kb2, Kb + (p*16 + rin16)*HD + 64);
                mma16808(c[2*p],   aq2[0], aq2[1], kb2[0]);
                mma16808(c[2*p+1], aq2[0], aq2[1], kb2[1]);
            }
        }

        // ---- softmax, no max subtraction ----
        float sum0 = 0.f, sum1 = 0.f;
#pragma unroll
        for (int n = 0; n < 8; ++n) {
            c[n][0] = __expf(c[n][0]);
            c[n][1] = __expf(c[n][1]);
            c[n][2] = __expf(c[n][2]);
            c[n][3] = __expf(c[n][3]);
            sum0 += c[n][0] + c[n][1];
            sum1 += c[n][2] + c[n][3];
        }
        sum0 += __shfl_xor_sync(0xffffffffu, sum0, 1);
        sum0 += __shfl_xor_sync(0xffffffffu, sum0, 2);
        sum1 += __shfl_xor_sync(0xffffffffu, sum1, 1);
        sum1 += __shfl_xor_sync(0xffffffffu, sum1, 2);
        l0 += sum0;
        l1 += sum1;

        unsigned pa[4][4];
#pragma unroll
        for (int k2 = 0; k2 < 4; ++k2) {
            pa[k2][0] = h2u(__floats2half2_rn(c[2*k2][0],   c[2*k2][1]));
            pa[k2][1] = h2u(__floats2half2_rn(c[2*k2][2],   c[2*k2][3]));
            pa[k2][2] = h2u(__floats2half2_rn(c[2*k2+1][0], c[2*k2+1][1]));
            pa[k2][3] = h2u(__floats2half2_rn(c[2*k2+1][2], c[2*k2+1][3]));
        }

        // ---- O += P @ V ----
#pragma unroll
        for (int k2 = 0; k2 < 4; ++k2) {
            const int srow = k2*16 + v_sin;
#pragma unroll
            for (int p2 = 0; p2 < 4; ++p2) {
                unsigned q[4];
                ldsm4t(q, Vb + srow*HD + (2*p2 + v_doff)*8);
                mma16816(o[2*p2],   pa[k2], q[0], q[1]);
                mma16816(o[2*p2+1], pa[k2], q[2], q[3]);
            }
            {
                unsigned q2[2];
                ldsm2t(q2, Vb + (k2*16 + v_sin)*HD + 64);
                mma16816(o[8], pa[k2], q2[0], q2[1]);
            }
        }
        // this warp's reads of slot are done
        if (lane == 0) mbar_arrive(mb + 32 + slot*8);
    }

    // ---- epilogue ----
    const float inv0 = 1.0f / l0, inv1 = 1.0f / l1;
    const int q0 = qt*128 + warp*16 + g;
    __half* base0 = g_ah + ((size_t)(b*SEQ + q0)     * HIDDEN) + h*HD;
    __half* base1 = g_ah + ((size_t)(b*SEQ + q0 + 8) * HIDDEN) + h*HD;
#pragma unroll
    for (int n = 0; n < 9; ++n) {
        const int d = n*8 + 2*t;
        *(__half2*)&base0[d] = __floats2half2_rn(o[n][0]*inv0, o[n][1]*inv0);
        *(__half2*)&base1[d] = __floats2half2_rn(o[n][2]*inv1, o[n][3]*inv1);
    }
}

// ---------------- host: tensor-map encode via driver entry point ----------------
typedef CUresult (*PFN_tmeTiled_v12)(CUtensorMap*, CUtensorMapDataType, cuuint32_t,
                                     void*, const cuuint64_t*, const cuuint64_t*,
                                     const cuuint32_t*, const cuuint32_t*,
                                     CUtensorMapInterleave, CUtensorMapSwizzle,
                                     CUtensorMapL2promotion, CUtensorMapFloatOOBfill);

static void make_map(PFN_tmeTiled_v12 enc, CUtensorMap* m, void* addr,
                     unsigned long long cols, unsigned long long rows,
                     unsigned box_rows) {
    cuuint64_t dims[2]   = {cols, rows};
    cuuint64_t stride[1] = {cols * 2};
    cuuint32_t box[2]    = {64u, box_rows};
    cuuint32_t es[2]     = {1u, 1u};
    enc(m, CU_TENSOR_MAP_DATA_TYPE_FLOAT16, 2, addr, dims, stride, box, es,
        CU_TENSOR_MAP_INTERLEAVE_NONE, CU_TENSOR_MAP_SWIZZLE_128B,
        CU_TENSOR_MAP_L2_PROMOTION_L2_128B, CU_TENSOR_MAP_FLOAT_OOB_FILL_NONE);
}

static void make_map_attn(PFN_tmeTiled_v12 enc, CUtensorMap* m, void* addr,
                          unsigned box_rows) {
    cuuint64_t dims[2]   = {HD, (cuuint64_t)BATCH*HEADS*SEQ};
    cuuint64_t stride[1] = {HD * 2};
    cuuint32_t box[2]    = {HD, box_rows};
    cuuint32_t es[2]     = {1u, 1u};
    enc(m, CU_TENSOR_MAP_DATA_TYPE_FLOAT16, 2, addr, dims, stride, box, es,
        CU_TENSOR_MAP_INTERLEAVE_NONE, CU_TENSOR_MAP_SWIZZLE_NONE,
        CU_TENSOR_MAP_L2_PROMOTION_L2_128B, CU_TENSOR_MAP_FLOAT_OOB_FILL_NONE);
}

// ---------------- launch ----------------
extern "C" void kernel_launch(void* const* d_in, const int* in_sizes, int n_in,
                              void* d_out, int out_size) {
    const float* x      = (const float*)d_in[0];
    const float* w_qkv  = (const float*)d_in[1];
    const float* b_qkv  = (const float*)d_in[2];
    const float* q_gamma= (const float*)d_in[3];
    const float* k_gamma= (const float*)d_in[4];
    const float* w_proj = (const float*)d_in[5];
    const float* b_proj = (const float*)d_in[6];
    float* out = (float*)d_out;

    cudaFuncSetAttribute(gemm_f16_kernel, cudaFuncAttributeMaxDynamicSharedMemorySize, GEMM_SMEM);
    cudaFuncSetAttribute(attn_f16_kernel, cudaFuncAttributeMaxDynamicSharedMemorySize, ATTN_SMEM);

    __half *xh, *wqh, *wph, *ah, *qh, *kh, *vh;
    cudaGetSymbolAddress((void**)&xh,  g_xh);
    cudaGetSymbolAddress((void**)&wqh, g_wqh);
    cudaGetSymbolAddress((void**)&wph, g_wph);
    cudaGetSymbolAddress((void**)&ah,  g_ah);
    cudaGetSymbolAddress((void**)&qh,  g_qh);
    cudaGetSymbolAddress((void**)&kh,  g_kh);
    cudaGetSymbolAddress((void**)&vh,  g_vh);

    void* fptr = nullptr;
    cudaDriverEntryPointQueryResult qres;
    cudaGetDriverEntryPointByVersion("cuTensorMapEncodeTiled", &fptr, 12000,
                                     cudaEnableDefault, &qres);
    PFN_tmeTiled_v12 enc = (PFN_tmeTiled_v12)fptr;

    CUtensorMap mAq, mBq, mAp, mBp, mQ, mK, mV;
    make_map(enc, &mAq, xh,  HIDDEN, M_TOT,  256);
    make_map(enc, &mBq, wqh, HIDDEN, N_QKV,  128);
    make_map(enc, &mAp, ah,  HIDDEN, M_TOT,  256);
    make_map(enc, &mBp, wph, HIDDEN, HIDDEN, 128);
    make_map_attn(enc, &mQ, qh, 128);
    make_map_attn(enc, &mK, kh, 64);
    make_map_attn(enc, &mV, vh, 64);

    {   // merged fp32 -> fp16 conversion (single launch)
        const int total = N8X + N8Q + N8P;
        conv_all_kernel<<<(total + 255)/256, 256>>>(
            (const float4*)x, (const float4*)w_qkv, (const float4*)w_proj,
            (uint4*)xh, (uint4*)wqh, (uint4*)wph);
    }
    {   // QKV projection
        dim3 grid(N_QKV/128, M_TOT/256);   // (27, 64)
        gemm_f16_kernel<<<grid, 288, GEMM_SMEM>>>(mAq, mBq, b_qkv, nullptr, 0);
    }
    {   // fused RMSNorm
        dim3 grid(BATCH*HEADS*SEQ/8, 2);
        rmsnorm_h_kernel<<<grid, 256>>>(q_gamma, k_gamma);
    }
    {   // attention (TMA-fed, decoupled)
        dim3 grid(SEQ/128, HEADS, BATCH);  // (8,16,16)
        attn_f16_kernel<<<grid, 256, ATTN_SMEM>>>(mQ, mK, mV);
    }
    {   // output projection
        dim3 grid(HIDDEN/128, M_TOT/256);  // (9, 64)
        gemm_f16_kernel<<<grid, 288, GEMM_SMEM>>>(mAp, mBp, b_proj, out, 1);
    }
}